// round 1
// baseline (speedup 1.0000x reference)
#include <cuda_runtime.h>

#define BB 8
#define CC 512
#define DQ 64
#define HH 128
#define WW 128
#define HWW 16384
#define GAMMA_ 1.0f

// ---------------- scratch (device globals; no allocation) ----------------
__device__ float g_q [BB*DQ*HWW];        // [B,DQ,H,W]
__device__ float g_k [BB*DQ*HWW];        // [B,DQ,H,W]
__device__ float g_v [BB*CC*HWW];        // [B,C ,H,W]
__device__ float g_qT[BB*WW*DQ*HH];      // [B,W,DQ,H]
__device__ float g_kT[BB*WW*DQ*HH];      // [B,W,DQ,H]
__device__ float g_vT[BB*WW*CC*HH];      // [B,W,C ,H]
__device__ float g_eH[BB*WW*HH*HH];      // [B,W,H,G]  (energy then att_H in-place)
__device__ float g_eW[BB*HH*WW*WW];      // [B,H,W,V]  (energy then att_W in-place)
__device__ float g_oH[BB*WW*CC*HH];      // [B,W,C,H]  out_H (transposed)

// ---------------- projection GEMM: out[b,d,p] = bias[d] + sum_c W[c,d]*x[b,c,p] ----
template<int D>
__device__ __forceinline__ void proj_body(const float* __restrict__ x,
                                          const float* __restrict__ Wm,
                                          const float* __restrict__ bias,
                                          float* __restrict__ out)
{
    const int pTile = blockIdx.x * 64;
    const int dTile = blockIdx.y * 64;
    const int b     = blockIdx.z;
    const int tid = threadIdx.x;
    const int tx = tid & 15, ty = tid >> 4;

    __shared__ float sW[16][65];
    __shared__ float sX[16][65];

    const float* xb = x + (size_t)b*CC*HWW + pTile;
    float acc[4][4] = {};

    for (int k0 = 0; k0 < CC; k0 += 16) {
        #pragma unroll
        for (int i = 0; i < 4; i++) {
            int e = tid + i*256;
            int kk = e >> 6, dd = e & 63;
            sW[kk][dd] = Wm[(size_t)(k0+kk)*D + dTile + dd];
            sX[kk][dd] = xb[(size_t)(k0+kk)*HWW + dd];
        }
        __syncthreads();
        #pragma unroll
        for (int kk = 0; kk < 16; kk++) {
            float a[4], c[4];
            #pragma unroll
            for (int i = 0; i < 4; i++) a[i] = sW[kk][ty + i*16];
            #pragma unroll
            for (int j = 0; j < 4; j++) c[j] = sX[kk][tx + j*16];
            #pragma unroll
            for (int i = 0; i < 4; i++)
                #pragma unroll
                for (int j = 0; j < 4; j++)
                    acc[i][j] += a[i]*c[j];
        }
        __syncthreads();
    }
    #pragma unroll
    for (int i = 0; i < 4; i++) {
        int d = dTile + ty + i*16;
        float bvv = bias[d];
        #pragma unroll
        for (int j = 0; j < 4; j++)
            out[(size_t)b*D*HWW + (size_t)d*HWW + pTile + tx + j*16] = acc[i][j] + bvv;
    }
}

__global__ void __launch_bounds__(256) proj_q_kernel(const float* x, const float* Wm, const float* bi){ proj_body<DQ>(x, Wm, bi, g_q); }
__global__ void __launch_bounds__(256) proj_k_kernel(const float* x, const float* Wm, const float* bi){ proj_body<DQ>(x, Wm, bi, g_k); }
__global__ void __launch_bounds__(256) proj_v_kernel(const float* x, const float* Wm, const float* bi){ proj_body<CC>(x, Wm, bi, g_v); }

// ---------------- transpose [B,D,H,W] -> [B,W,D,H] ----------------
__device__ __forceinline__ void transpose_body(const float* __restrict__ src,
                                               float* __restrict__ dst, int D)
{
    __shared__ float t[32][33];
    int bd = blockIdx.z;
    int b = bd / D, d = bd - b*D;
    int w0 = blockIdx.x*32, h0 = blockIdx.y*32;
    const float* s = src + (size_t)bd*HWW;
    int tx = threadIdx.x, ty = threadIdx.y;
    #pragma unroll
    for (int k = 0; k < 32; k += 8)
        t[ty+k][tx] = s[(size_t)(h0+ty+k)*WW + w0 + tx];   // t[h_local][w_local]
    __syncthreads();
    #pragma unroll
    for (int k = 0; k < 32; k += 8) {
        int w = w0 + ty + k;
        int h = h0 + tx;
        dst[(((size_t)b*WW + w)*D + d)*HH + h] = t[tx][ty+k];
    }
}
__global__ void transpose_q_kernel(){ transpose_body(g_q, g_qT, DQ); }
__global__ void transpose_k_kernel(){ transpose_body(g_k, g_kT, DQ); }
__global__ void transpose_v_kernel(){ transpose_body(g_v, g_vT, CC); }

// ---------------- energy: E[i,j] = sum_c q[c*cs+i]*k[c*cs+j] (K=64), per slice ----
template<int MASK>
__device__ __forceinline__ void energy_body(const float* __restrict__ qg,
                                            const float* __restrict__ kg,
                                            float* __restrict__ eg,
                                            long strideB, long strideS, int S1, long cStride)
{
    int s = blockIdx.x;
    int sb = s / S1, ss = s - sb*S1;
    long base = (long)sb*strideB + (long)ss*strideS;
    const float* q = qg + base;
    const float* k = kg + base;
    float* E = eg + (size_t)s * (HH*WW);

    __shared__ float sQ[32][128];
    __shared__ float sK[32][128];
    int tid = threadIdx.x;
    int tx = tid & 15, ty = tid >> 4;
    float acc[8][8] = {};
    for (int c0 = 0; c0 < DQ; c0 += 32) {
        #pragma unroll
        for (int i = 0; i < 16; i++) {
            int e = tid + i*256;
            int cc = e >> 7, ii = e & 127;
            sQ[cc][ii] = q[(size_t)(c0+cc)*cStride + ii];
            sK[cc][ii] = k[(size_t)(c0+cc)*cStride + ii];
        }
        __syncthreads();
        #pragma unroll
        for (int cc = 0; cc < 32; cc++) {
            float a[8], bb[8];
            #pragma unroll
            for (int i = 0; i < 8; i++) a[i]  = sQ[cc][ty + i*16];
            #pragma unroll
            for (int j = 0; j < 8; j++) bb[j] = sK[cc][tx + j*16];
            #pragma unroll
            for (int i = 0; i < 8; i++)
                #pragma unroll
                for (int j = 0; j < 8; j++)
                    acc[i][j] += a[i]*bb[j];
        }
        __syncthreads();
    }
    #pragma unroll
    for (int i = 0; i < 8; i++) {
        int ii = ty + i*16;
        #pragma unroll
        for (int j = 0; j < 8; j++) {
            int jj = tx + j*16;
            float v = acc[i][j];
            if (MASK && ii == jj) v = __int_as_float(0xff800000); // -inf (diag mask)
            E[ii*128 + jj] = v;
        }
    }
}
__global__ void __launch_bounds__(256) energy_H_kernel(){
    energy_body<1>(g_qT, g_kT, g_eH, (long)WW*DQ*HH, (long)DQ*HH, WW, HH);
}
__global__ void __launch_bounds__(256) energy_W_kernel(){
    energy_body<0>(g_q,  g_k,  g_eW, (long)DQ*HWW, (long)WW, HH, HWW);
}

// ---------------- softmax over concat(eH row, eW row), warp per pixel ----------------
__global__ void __launch_bounds__(256) softmax_kernel()
{
    int gwarp = blockIdx.x * 8 + (threadIdx.x >> 5);
    int lane = threadIdx.x & 31;
    int b = gwarp >> 14;            // / 16384
    int rem = gwarp & 16383;
    int h = rem >> 7, w = rem & 127;
    float4* pH = (float4*)(g_eH + (((size_t)b*WW + w)*HH + h)*HH) + lane;
    float4* pW = (float4*)(g_eW + (((size_t)b*HH + h)*WW + w)*WW) + lane;
    float4 vH = *pH, vW = *pW;
    float m = fmaxf(fmaxf(fmaxf(vH.x,vH.y), fmaxf(vH.z,vH.w)),
                    fmaxf(fmaxf(vW.x,vW.y), fmaxf(vW.z,vW.w)));
    #pragma unroll
    for (int o = 16; o > 0; o >>= 1) m = fmaxf(m, __shfl_xor_sync(0xffffffffu, m, o));
    vH.x = __expf(vH.x-m); vH.y = __expf(vH.y-m); vH.z = __expf(vH.z-m); vH.w = __expf(vH.w-m);
    vW.x = __expf(vW.x-m); vW.y = __expf(vW.y-m); vW.z = __expf(vW.z-m); vW.w = __expf(vW.w-m);
    float ssum = (vH.x+vH.y)+(vH.z+vH.w)+(vW.x+vW.y)+(vW.z+vW.w);
    #pragma unroll
    for (int o = 16; o > 0; o >>= 1) ssum += __shfl_xor_sync(0xffffffffu, ssum, o);
    float inv = 1.0f/ssum;
    vH.x*=inv; vH.y*=inv; vH.z*=inv; vH.w*=inv;
    vW.x*=inv; vW.y*=inv; vW.z*=inv; vW.w*=inv;
    *pH = vH; *pW = vW;
}

// ---------------- aggregation: O[m,n] = sum_k V[m,k]*A[n,k]  (K=128, N=128, M=512) ----
__device__ __forceinline__ void agg_body(const float* __restrict__ vg,
                                         long vStrideB, long vStrideS, int S1, long vStrideM,
                                         const float* __restrict__ ag,
                                         float* __restrict__ og,
                                         long oStrideB, long oStrideS, long oStrideM)
{
    int s = blockIdx.z;
    int mTile = blockIdx.y * 64;
    int nTile = blockIdx.x * 64;
    int sb = s / S1, ss = s - sb*S1;
    const float* V = vg + (long)sb*vStrideB + (long)ss*vStrideS;
    const float* A = ag + (size_t)s*(HH*WW);
    float* O = og + (long)sb*oStrideB + (long)ss*oStrideS;

    __shared__ float sV[32][65];
    __shared__ float sA[32][65];
    int tid = threadIdx.x, tx = tid & 15, ty = tid >> 4;
    float acc[4][4] = {};
    for (int k0 = 0; k0 < HH; k0 += 32) {
        #pragma unroll
        for (int i = 0; i < 8; i++) {
            int e = tid + i*256;
            int mm = e >> 5, kk = e & 31;
            sV[kk][mm] = V[(size_t)(mTile+mm)*vStrideM + k0 + kk];
            sA[kk][mm] = A[(size_t)(nTile+mm)*HH + k0 + kk];
        }
        __syncthreads();
        #pragma unroll
        for (int kk = 0; kk < 32; kk++) {
            float a[4], bb[4];
            #pragma unroll
            for (int i = 0; i < 4; i++) a[i]  = sV[kk][ty + i*16];
            #pragma unroll
            for (int j = 0; j < 4; j++) bb[j] = sA[kk][tx + j*16];
            #pragma unroll
            for (int i = 0; i < 4; i++)
                #pragma unroll
                for (int j = 0; j < 4; j++)
                    acc[i][j] += a[i]*bb[j];
        }
        __syncthreads();
    }
    #pragma unroll
    for (int i = 0; i < 4; i++) {
        int mrow = mTile + ty + i*16;
        #pragma unroll
        for (int j = 0; j < 4; j++)
            O[(size_t)mrow*oStrideM + nTile + tx + j*16] = acc[i][j];
    }
}
__global__ void __launch_bounds__(256) agg_H_kernel(){
    // out_H[b,w,c,h] = sum_g vT[b,w,c,g] * aH[b,w,h,g]
    agg_body(g_vT, (long)WW*CC*HH, (long)CC*HH, WW, HH,
             g_eH, g_oH, (long)WW*CC*HH, (long)CC*HH, HH);
}
__global__ void __launch_bounds__(256) agg_W_kernel(float* out){
    // out_W[b,c,h,w] = sum_v v[b,c,h,v] * aW[b,h,w,v]  -> written raw into d_out
    agg_body(g_v, (long)CC*HWW, (long)WW, HH, HWW,
             g_eW, out, (long)CC*HWW, (long)WW, HWW);
}

// ---------------- combine: out = GAMMA*(out_H^T + out_W) + x ----------------
__global__ void combine_kernel(const float* __restrict__ x, float* __restrict__ out)
{
    __shared__ float t[32][33];
    int bc = blockIdx.z;
    int b = bc >> 9, c = bc & 511;     // /CC, %CC
    int w0 = blockIdx.x*32, h0 = blockIdx.y*32;
    int tx = threadIdx.x, ty = threadIdx.y;
    #pragma unroll
    for (int k = 0; k < 32; k += 8) {
        int w = w0 + ty + k;
        int h = h0 + tx;
        t[ty+k][tx] = g_oH[(((size_t)b*WW + w)*CC + c)*HH + h];   // t[w_local][h_local]
    }
    __syncthreads();
    #pragma unroll
    for (int k = 0; k < 32; k += 8) {
        int h = h0 + ty + k;
        int w = w0 + tx;
        size_t idx = ((size_t)bc*HH + h)*WW + w;
        out[idx] = GAMMA_*(t[tx][ty+k] + out[idx]) + x[idx];
    }
}

// ---------------- launch ----------------
extern "C" void kernel_launch(void* const* d_in, const int* in_sizes, int n_in,
                              void* d_out, int out_size)
{
    const float* x  = (const float*)d_in[0];
    const float* Wq = (const float*)d_in[1];
    const float* bq = (const float*)d_in[2];
    const float* Wk = (const float*)d_in[3];
    const float* bk = (const float*)d_in[4];
    const float* Wv = (const float*)d_in[5];
    const float* bv = (const float*)d_in[6];
    float* out = (float*)d_out;

    dim3 tb(32, 8);

    proj_q_kernel<<<dim3(HWW/64, 1,     BB), 256>>>(x, Wq, bq);
    proj_k_kernel<<<dim3(HWW/64, 1,     BB), 256>>>(x, Wk, bk);
    proj_v_kernel<<<dim3(HWW/64, CC/64, BB), 256>>>(x, Wv, bv);

    transpose_q_kernel<<<dim3(WW/32, HH/32, BB*DQ), tb>>>();
    transpose_k_kernel<<<dim3(WW/32, HH/32, BB*DQ), tb>>>();
    transpose_v_kernel<<<dim3(WW/32, HH/32, BB*CC), tb>>>();

    energy_H_kernel<<<BB*WW, 256>>>();
    energy_W_kernel<<<BB*HH, 256>>>();

    softmax_kernel<<<(BB*HH*WW)/8, 256>>>();

    agg_H_kernel<<<dim3(HH/64, CC/64, BB*WW), 256>>>();
    agg_W_kernel<<<dim3(WW/64, CC/64, BB*HH), 256>>>(out);

    combine_kernel<<<dim3(WW/32, HH/32, BB*CC), tb>>>(x, out);
}

// round 3
// speedup vs baseline: 1.7415x; 1.7415x over previous
#include <cuda_runtime.h>
#include <cuda_bf16.h>
#include <cstdint>

#define BB 8
#define CC 512
#define DQ 64
#define HH 128
#define WW 128
#define HWW 16384
#define GAMMA_ 1.0f

// ---------------- scratch (device globals; no allocation) ----------------
__device__ float g_q [BB*DQ*HWW];        // [B,DQ,H,W]
__device__ float g_k [BB*DQ*HWW];        // [B,DQ,H,W]
__device__ float g_v [BB*CC*HWW];        // [B,C ,H,W]
__device__ float g_qT[BB*WW*DQ*HH];      // [B,W,DQ,H]
__device__ float g_kT[BB*WW*DQ*HH];      // [B,W,DQ,H]
__device__ float g_vT[BB*WW*CC*HH];      // [B,W,C ,H]
__device__ float g_eH[BB*WW*HH*HH];      // [B,W,H,G]
__device__ float g_eW[BB*HH*WW*WW];      // [B,H,W,V]
__device__ float g_oH[BB*WW*CC*HH];      // [B,W,C,H]

// packed bf16 hi/lo operands: uint32 = (bf16(k=2kp+1)<<16) | bf16(k=2kp)
__device__ uint32_t g_xp_h[(size_t)BB*256*HWW];   // [b][kp][p]
__device__ uint32_t g_xp_l[(size_t)BB*256*HWW];
__device__ uint32_t g_Wp_h[256*640];              // [kp][m]  m: 0-63 Wq, 64-127 Wk, 128-639 Wv
__device__ uint32_t g_Wp_l[256*640];

// ---------------- helpers ----------------
__device__ __forceinline__ void split_pack(float v0, float v1, uint32_t& hi, uint32_t& lo){
    __nv_bfloat16 h0 = __float2bfloat16(v0);
    __nv_bfloat16 h1 = __float2bfloat16(v1);
    __nv_bfloat16 l0 = __float2bfloat16(v0 - __bfloat162float(h0));
    __nv_bfloat16 l1 = __float2bfloat16(v1 - __bfloat162float(h1));
    hi = ((uint32_t)__bfloat16_as_ushort(h1) << 16) | (uint32_t)__bfloat16_as_ushort(h0);
    lo = ((uint32_t)__bfloat16_as_ushort(l1) << 16) | (uint32_t)__bfloat16_as_ushort(l0);
}

__device__ __forceinline__ void mma_bf16(float* c, const uint32_t* a, const uint32_t* b){
    asm volatile("mma.sync.aligned.m16n8k16.row.col.f32.bf16.bf16.f32 "
        "{%0,%1,%2,%3}, {%4,%5,%6,%7}, {%8,%9}, {%0,%1,%2,%3};"
        : "+f"(c[0]), "+f"(c[1]), "+f"(c[2]), "+f"(c[3])
        : "r"(a[0]), "r"(a[1]), "r"(a[2]), "r"(a[3]), "r"(b[0]), "r"(b[1]));
}

// ---------------- pack kernels ----------------
// x [B,C,H,W] -> g_xp_h/l [b][kp][p] (uint4 over 4 consecutive p)
__global__ void __launch_bounds__(256) pack_x_kernel(const float* __restrict__ x)
{
    int u = blockIdx.x * 256 + threadIdx.x;        // (b, kp, p4)
    int b = u >> 20;
    int kp = (u >> 12) & 255;
    int p4 = u & 4095;
    const float4 a0 = *(const float4*)(x + ((size_t)b*CC + 2*kp  )*HWW + p4*4);
    const float4 a1 = *(const float4*)(x + ((size_t)b*CC + 2*kp+1)*HWW + p4*4);
    uint4 hi, lo;
    split_pack(a0.x, a1.x, hi.x, lo.x);
    split_pack(a0.y, a1.y, hi.y, lo.y);
    split_pack(a0.z, a1.z, hi.z, lo.z);
    split_pack(a0.w, a1.w, hi.w, lo.w);
    size_t o = (((size_t)b*256 + kp)*HWW) + p4*4;
    *(uint4*)(g_xp_h + o) = hi;
    *(uint4*)(g_xp_l + o) = lo;
}

// W (Wq[c][64], Wk[c][64], Wv[c][512]) -> g_Wp_h/l [kp][m], m in 0..639
__global__ void __launch_bounds__(256) pack_W_kernel(const float* __restrict__ Wq,
                                                     const float* __restrict__ Wk,
                                                     const float* __restrict__ Wv)
{
    int u = blockIdx.x * 256 + threadIdx.x;        // (kp, m4) : 256*160
    if (u >= 256*160) return;
    int kp = u / 160;
    int m4 = u - kp*160;
    int m = m4*4;
    int c0 = 2*kp, c1 = 2*kp+1;
    float v0[4], v1[4];
    #pragma unroll
    for (int j = 0; j < 4; j++) {
        int mm = m + j;
        if (mm < 64)       { v0[j] = Wq[(size_t)c0*DQ + mm];       v1[j] = Wq[(size_t)c1*DQ + mm]; }
        else if (mm < 128) { v0[j] = Wk[(size_t)c0*DQ + mm-64];    v1[j] = Wk[(size_t)c1*DQ + mm-64]; }
        else               { v0[j] = Wv[(size_t)c0*CC + mm-128];   v1[j] = Wv[(size_t)c1*CC + mm-128]; }
    }
    uint4 hi, lo;
    split_pack(v0[0], v1[0], hi.x, lo.x);
    split_pack(v0[1], v1[1], hi.y, lo.y);
    split_pack(v0[2], v1[2], hi.z, lo.z);
    split_pack(v0[3], v1[3], hi.w, lo.w);
    *(uint4*)(g_Wp_h + (size_t)kp*640 + m) = hi;
    *(uint4*)(g_Wp_l + (size_t)kp*640 + m) = lo;
}

// ---------------- HMMA projection GEMM ----------------
// out[m, p] = bias[m] + sum_c A[m,c]*x[c,p]; split-bf16 3-pass (hh + hl + lh)
// CTA: 128(M) x 128(N), K-chunk 32 (16 kp). 8 warps (2x4), warp tile 64x32.
__global__ void __launch_bounds__(256) mma_proj_kernel(
    const float* __restrict__ bq, const float* __restrict__ bk, const float* __restrict__ bvv)
{
    __shared__ uint32_t sAh[16][136], sAl[16][136], sBh[16][136], sBl[16][136];

    const int tid = threadIdx.x;
    const int wid = tid >> 5, lane = tid & 31;
    const int gid = lane >> 2, tig = lane & 3;
    const int wm0 = (wid >> 2) * 64;
    const int wn0 = (wid & 3) * 32;
    const int mTile = blockIdx.x * 128;            // 0..4 -> rows in [0,640)
    const int nTile = blockIdx.y * 128;
    const int b = blockIdx.z;

    float acc[4][4][4];
    #pragma unroll
    for (int i = 0; i < 4; i++)
        #pragma unroll
        for (int j = 0; j < 4; j++)
            #pragma unroll
            for (int r = 0; r < 4; r++) acc[i][j][r] = 0.f;

    const size_t xBase = ((size_t)b*256)*HWW + nTile;

    for (int it = 0; it < 16; ++it) {
        const int kp0 = it * 16;
        #pragma unroll
        for (int i = 0; i < 2; i++) {
            int f = tid + i*256;
            int kp = f >> 5, c4 = (f & 31) * 4;
            *(uint4*)&sAh[kp][c4] = *(const uint4*)&g_Wp_h[(size_t)(kp0+kp)*640 + mTile + c4];
            *(uint4*)&sAl[kp][c4] = *(const uint4*)&g_Wp_l[(size_t)(kp0+kp)*640 + mTile + c4];
            *(uint4*)&sBh[kp][c4] = *(const uint4*)&g_xp_h[xBase + (size_t)(kp0+kp)*HWW + c4];
            *(uint4*)&sBl[kp][c4] = *(const uint4*)&g_xp_l[xBase + (size_t)(kp0+kp)*HWW + c4];
        }
        __syncthreads();
        #pragma unroll
        for (int ks = 0; ks < 2; ks++) {
            const int kb = ks * 8;
            uint32_t ah[4][4], al[4][4], bh[4][2], bl[4][2];
            #pragma unroll
            for (int mi = 0; mi < 4; mi++) {
                int m = wm0 + mi*16 + gid;
                ah[mi][0] = sAh[kb+tig  ][m];
                ah[mi][1] = sAh[kb+tig  ][m+8];
                ah[mi][2] = sAh[kb+tig+4][m];
                ah[mi][3] = sAh[kb+tig+4][m+8];
                al[mi][0] = sAl[kb+tig  ][m];
                al[mi][1] = sAl[kb+tig  ][m+8];
                al[mi][2] = sAl[kb+tig+4][m];
                al[mi][3] = sAl[kb+tig+4][m+8];
            }
            #pragma unroll
            for (int nj = 0; nj < 4; nj++) {
                int n = wn0 + nj*8 + gid;
                bh[nj][0] = sBh[kb+tig  ][n];
                bh[nj][1] = sBh[kb+tig+4][n];
                bl[nj][0] = sBl[kb+tig  ][n];
                bl[nj][1] = sBl[kb+tig+4][n];
            }
            #pragma unroll
            for (int mi = 0; mi < 4; mi++)
                #pragma unroll
                for (int nj = 0; nj < 4; nj++) {
                    mma_bf16(acc[mi][nj], ah[mi], bh[nj]);
                    mma_bf16(acc[mi][nj], ah[mi], bl[nj]);
                    mma_bf16(acc[mi][nj], al[mi], bh[nj]);
                }
        }
        __syncthreads();
    }

    // epilogue: resolve output array + bias per row, write float2 (c pairs)
    #pragma unroll
    for (int mi = 0; mi < 4; mi++) {
        int rows[2];
        rows[0] = mTile + wm0 + mi*16 + gid;
        rows[1] = rows[0] + 8;
        #pragma unroll
        for (int half = 0; half < 2; half++) {
            int row = rows[half];
            float bias; float* optr;
            if (row < 64)       { bias = bq[row];      optr = g_q + ((size_t)b*DQ + row)      *HWW; }
            else if (row < 128) { bias = bk[row-64];   optr = g_k + ((size_t)b*DQ + (row-64)) *HWW; }
            else                { bias = bvv[row-128]; optr = g_v + ((size_t)b*CC + (row-128))*HWW; }
            #pragma unroll
            for (int nj = 0; nj < 4; nj++) {
                int col = nTile + wn0 + nj*8 + 2*tig;
                float2 f2;
                f2.x = acc[mi][nj][half*2+0] + bias;
                f2.y = acc[mi][nj][half*2+1] + bias;
                *(float2*)(optr + col) = f2;
            }
        }
    }
}

// ---------------- transpose [B,D,H,W] -> [B,W,D,H] ----------------
__device__ __forceinline__ void transpose_body(const float* __restrict__ src,
                                               float* __restrict__ dst, int D)
{
    __shared__ float t[32][33];
    int bd = blockIdx.z;
    int b = bd / D, d = bd - b*D;
    int w0 = blockIdx.x*32, h0 = blockIdx.y*32;
    const float* s = src + (size_t)bd*HWW;
    int tx = threadIdx.x, ty = threadIdx.y;
    #pragma unroll
    for (int k = 0; k < 32; k += 8)
        t[ty+k][tx] = s[(size_t)(h0+ty+k)*WW + w0 + tx];
    __syncthreads();
    #pragma unroll
    for (int k = 0; k < 32; k += 8) {
        int w = w0 + ty + k;
        int h = h0 + tx;
        dst[(((size_t)b*WW + w)*D + d)*HH + h] = t[tx][ty+k];
    }
}
__global__ void transpose_q_kernel(){ transpose_body(g_q, g_qT, DQ); }
__global__ void transpose_k_kernel(){ transpose_body(g_k, g_kT, DQ); }
__global__ void transpose_v_kernel(){ transpose_body(g_v, g_vT, CC); }

// ---------------- energy ----------------
template<int MASK>
__device__ __forceinline__ void energy_body(const float* __restrict__ qg,
                                            const float* __restrict__ kg,
                                            float* __restrict__ eg,
                                            long strideB, long strideS, int S1, long cStride)
{
    int s = blockIdx.x;
    int sb = s / S1, ss = s - sb*S1;
    long base = (long)sb*strideB + (long)ss*strideS;
    const float* q = qg + base;
    const float* k = kg + base;
    float* E = eg + (size_t)s * (HH*WW);

    __shared__ float sQ[32][128];
    __shared__ float sK[32][128];
    int tid = threadIdx.x;
    int tx = tid & 15, ty = tid >> 4;
    float acc[8][8] = {};
    for (int c0 = 0; c0 < DQ; c0 += 32) {
        #pragma unroll
        for (int i = 0; i < 16; i++) {
            int e = tid + i*256;
            int cc = e >> 7, ii = e & 127;
            sQ[cc][ii] = q[(size_t)(c0+cc)*cStride + ii];
            sK[cc][ii] = k[(size_t)(c0+cc)*cStride + ii];
        }
        __syncthreads();
        #pragma unroll
        for (int cc = 0; cc < 32; cc++) {
            float a[8], bb[8];
            #pragma unroll
            for (int i = 0; i < 8; i++) a[i]  = sQ[cc][ty + i*16];
            #pragma unroll
            for (int j = 0; j < 8; j++) bb[j] = sK[cc][tx + j*16];
            #pragma unroll
            for (int i = 0; i < 8; i++)
                #pragma unroll
                for (int j = 0; j < 8; j++)
                    acc[i][j] += a[i]*bb[j];
        }
        __syncthreads();
    }
    #pragma unroll
    for (int i = 0; i < 8; i++) {
        int ii = ty + i*16;
        #pragma unroll
        for (int j = 0; j < 8; j++) {
            int jj = tx + j*16;
            float v = acc[i][j];
            if (MASK && ii == jj) v = __int_as_float(0xff800000);
            E[ii*128 + jj] = v;
        }
    }
}
__global__ void __launch_bounds__(256) energy_H_kernel(){
    energy_body<1>(g_qT, g_kT, g_eH, (long)WW*DQ*HH, (long)DQ*HH, WW, HH);
}
__global__ void __launch_bounds__(256) energy_W_kernel(){
    energy_body<0>(g_q,  g_k,  g_eW, (long)DQ*HWW, (long)WW, HH, HWW);
}

// ---------------- softmax ----------------
__global__ void __launch_bounds__(256) softmax_kernel()
{
    int gwarp = blockIdx.x * 8 + (threadIdx.x >> 5);
    int lane = threadIdx.x & 31;
    int b = gwarp >> 14;
    int rem = gwarp & 16383;
    int h = rem >> 7, w = rem & 127;
    float4* pH = (float4*)(g_eH + (((size_t)b*WW + w)*HH + h)*HH) + lane;
    float4* pW = (float4*)(g_eW + (((size_t)b*HH + h)*WW + w)*WW) + lane;
    float4 vH = *pH, vW = *pW;
    float m = fmaxf(fmaxf(fmaxf(vH.x,vH.y), fmaxf(vH.z,vH.w)),
                    fmaxf(fmaxf(vW.x,vW.y), fmaxf(vW.z,vW.w)));
    #pragma unroll
    for (int o = 16; o > 0; o >>= 1) m = fmaxf(m, __shfl_xor_sync(0xffffffffu, m, o));
    vH.x = __expf(vH.x-m); vH.y = __expf(vH.y-m); vH.z = __expf(vH.z-m); vH.w = __expf(vH.w-m);
    vW.x = __expf(vW.x-m); vW.y = __expf(vW.y-m); vW.z = __expf(vW.z-m); vW.w = __expf(vW.w-m);
    float ssum = (vH.x+vH.y)+(vH.z+vH.w)+(vW.x+vW.y)+(vW.z+vW.w);
    #pragma unroll
    for (int o = 16; o > 0; o >>= 1) ssum += __shfl_xor_sync(0xffffffffu, ssum, o);
    float inv = 1.0f/ssum;
    vH.x*=inv; vH.y*=inv; vH.z*=inv; vH.w*=inv;
    vW.x*=inv; vW.y*=inv; vW.z*=inv; vW.w*=inv;
    *pH = vH; *pW = vW;
}

// ---------------- aggregation ----------------
__device__ __forceinline__ void agg_body(const float* __restrict__ vg,
                                         long vStrideB, long vStrideS, int S1, long vStrideM,
                                         const float* __restrict__ ag,
                                         float* __restrict__ og,
                                         long oStrideB, long oStrideS, long oStrideM)
{
    int s = blockIdx.z;
    int mTile = blockIdx.y * 64;
    int nTile = blockIdx.x * 64;
    int sb = s / S1, ss = s - sb*S1;
    const float* V = vg + (long)sb*vStrideB + (long)ss*vStrideS;
    const float* A = ag + (size_t)s*(HH*WW);
    float* O = og + (long)sb*oStrideB + (long)ss*oStrideS;

    __shared__ float sV[32][65];
    __shared__ float sA[32][65];
    int tid = threadIdx.x, tx = tid & 15, ty = tid >> 4;
    float acc[4][4] = {};
    for (int k0 = 0; k0 < HH; k0 += 32) {
        #pragma unroll
        for (int i = 0; i < 8; i++) {
            int e = tid + i*256;
            int mm = e >> 5, kk = e & 31;
            sV[kk][mm] = V[(size_t)(mTile+mm)*vStrideM + k0 + kk];
            sA[kk][mm] = A[(size_t)(nTile+mm)*HH + k0 + kk];
        }
        __syncthreads();
        #pragma unroll
        for (int kk = 0; kk < 32; kk++) {
            float a[4], bb[4];
            #pragma unroll
            for (int i = 0; i < 4; i++) a[i]  = sV[kk][ty + i*16];
            #pragma unroll
            for (int j = 0; j < 4; j++) bb[j] = sA[kk][tx + j*16];
            #pragma unroll
            for (int i = 0; i < 4; i++)
                #pragma unroll
                for (int j = 0; j < 4; j++)
                    acc[i][j] += a[i]*bb[j];
        }
        __syncthreads();
    }
    #pragma unroll
    for (int i = 0; i < 4; i++) {
        int mrow = mTile + ty + i*16;
        #pragma unroll
        for (int j = 0; j < 4; j++)
            O[(size_t)mrow*oStrideM + nTile + tx + j*16] = acc[i][j];
    }
}
__global__ void __launch_bounds__(256) agg_H_kernel(){
    agg_body(g_vT, (long)WW*CC*HH, (long)CC*HH, WW, HH,
             g_eH, g_oH, (long)WW*CC*HH, (long)CC*HH, HH);
}
__global__ void __launch_bounds__(256) agg_W_kernel(float* out){
    agg_body(g_v, (long)CC*HWW, (long)WW, HH, HWW,
             g_eW, out, (long)CC*HWW, (long)WW, HWW);
}

// ---------------- combine ----------------
__global__ void combine_kernel(const float* __restrict__ x, float* __restrict__ out)
{
    __shared__ float t[32][33];
    int bc = blockIdx.z;
    int b = bc >> 9, c = bc & 511;
    int w0 = blockIdx.x*32, h0 = blockIdx.y*32;
    int tx = threadIdx.x, ty = threadIdx.y;
    #pragma unroll
    for (int k = 0; k < 32; k += 8) {
        int w = w0 + ty + k;
        int h = h0 + tx;
        t[ty+k][tx] = g_oH[(((size_t)b*WW + w)*CC + c)*HH + h];
    }
    __syncthreads();
    #pragma unroll
    for (int k = 0; k < 32; k += 8) {
        int h = h0 + ty + k;
        int w = w0 + tx;
        size_t idx = ((size_t)bc*HH + h)*WW + w;
        out[idx] = GAMMA_*(t[tx][ty+k] + out[idx]) + x[idx];
    }
}

// ---------------- launch ----------------
extern "C" void kernel_launch(void* const* d_in, const int* in_sizes, int n_in,
                              void* d_out, int out_size)
{
    const float* x  = (const float*)d_in[0];
    const float* Wq = (const float*)d_in[1];
    const float* bq = (const float*)d_in[2];
    const float* Wk = (const float*)d_in[3];
    const float* bk = (const float*)d_in[4];
    const float* Wv = (const float*)d_in[5];
    const float* bv = (const float*)d_in[6];
    float* out = (float*)d_out;

    dim3 tb(32, 8);

    pack_W_kernel<<<160, 256>>>(Wq, Wk, Wv);
    pack_x_kernel<<<(BB*256*HWW/4)/256, 256>>>(x);

    mma_proj_kernel<<<dim3(5, HWW/128, BB), 256>>>(bq, bk, bv);

    transpose_q_kernel<<<dim3(WW/32, HH/32, BB*DQ), tb>>>();
    transpose_k_kernel<<<dim3(WW/32, HH/32, BB*DQ), tb>>>();
    transpose_v_kernel<<<dim3(WW/32, HH/32, BB*CC), tb>>>();

    energy_H_kernel<<<BB*WW, 256>>>();
    energy_W_kernel<<<BB*HH, 256>>>();

    softmax_kernel<<<(BB*HH*WW)/8, 256>>>();

    agg_H_kernel<<<dim3(HH/64, CC/64, BB*WW), 256>>>();
    agg_W_kernel<<<dim3(WW/64, CC/64, BB*HH), 256>>>(out);

    combine_kernel<<<dim3(WW/32, HH/32, BB*CC), tb>>>(x, out);
}

// round 7
// speedup vs baseline: 2.3797x; 1.3665x over previous
#include <cuda_runtime.h>
#include <cuda_bf16.h>
#include <cstdint>

#define BB 8
#define CC 512
#define DQ 64
#define HH 128
#define WW 128
#define HWW 16384
#define GAMMA_ 1.0f

// ---------------- scratch (device globals; no allocation) ----------------
__device__ float g_q [BB*DQ*HWW];        // [B,DQ,H,W]
__device__ float g_k [BB*DQ*HWW];        // [B,DQ,H,W]
__device__ float g_v [BB*CC*HWW];        // [B,C ,H,W]
__device__ float g_qT[BB*WW*DQ*HH];      // [B,W,DQ,H]
__device__ float g_kT[BB*WW*DQ*HH];      // [B,W,DQ,H]
__device__ float g_vT[BB*WW*CC*HH];      // [B,W,C ,H]
__device__ float g_eH[BB*WW*HH*HH];      // [B,W,H,G]  energy -> att (in place)
__device__ float g_eW[BB*HH*WW*WW];      // [B,H,W,V]  energy -> att (in place)
__device__ float g_oH[BB*WW*CC*HH];      // [B,W,C,H]

// packed bf16 hi/lo (uint32 = two consecutive-K bf16, low half = even k)
__device__ uint32_t g_xp_h[(size_t)BB*256*HWW];    // [b][kp][p]
__device__ uint32_t g_xp_l[(size_t)BB*256*HWW];
__device__ uint32_t g_Wp_h[256*640];               // [kp][m]
__device__ uint32_t g_Wp_l[256*640];
// K-major operands for aggregation ([slice][kp=64][cols])
__device__ uint32_t g_vWkm_h[(size_t)BB*HH*64*512]; // [b*HH+h][vp][c]
__device__ uint32_t g_vWkm_l[(size_t)BB*HH*64*512];
__device__ uint32_t g_vHkm_h[(size_t)BB*WW*64*512]; // [b*WW+w][gp][c]
__device__ uint32_t g_vHkm_l[(size_t)BB*WW*64*512];
__device__ uint32_t g_aHkm_h[(size_t)BB*WW*64*128]; // [b*WW+w][gp][h]
__device__ uint32_t g_aHkm_l[(size_t)BB*WW*64*128];
__device__ uint32_t g_aWkm_h[(size_t)BB*HH*64*128]; // [b*HH+h][vp][w]
__device__ uint32_t g_aWkm_l[(size_t)BB*HH*64*128];

// ---------------- helpers ----------------
__device__ __forceinline__ void split_pack(float v0, float v1, uint32_t& hi, uint32_t& lo){
    __nv_bfloat16 h0 = __float2bfloat16(v0);
    __nv_bfloat16 h1 = __float2bfloat16(v1);
    __nv_bfloat16 l0 = __float2bfloat16(v0 - __bfloat162float(h0));
    __nv_bfloat16 l1 = __float2bfloat16(v1 - __bfloat162float(h1));
    hi = ((uint32_t)__bfloat16_as_ushort(h1) << 16) | (uint32_t)__bfloat16_as_ushort(h0);
    lo = ((uint32_t)__bfloat16_as_ushort(l1) << 16) | (uint32_t)__bfloat16_as_ushort(l0);
}

__device__ __forceinline__ void mma_bf16(float* c, const uint32_t* a, const uint32_t* b){
    asm volatile("mma.sync.aligned.m16n8k16.row.col.f32.bf16.bf16.f32 "
        "{%0,%1,%2,%3}, {%4,%5,%6,%7}, {%8,%9}, {%0,%1,%2,%3};"
        : "+f"(c[0]), "+f"(c[1]), "+f"(c[2]), "+f"(c[3])
        : "r"(a[0]), "r"(a[1]), "r"(a[2]), "r"(a[3]), "r"(b[0]), "r"(b[1]));
}

// ---------------- pack kernels (x, W) — harness pointers only ----------------
__global__ void __launch_bounds__(256) pack_x_kernel(const float* __restrict__ x)
{
    int u = blockIdx.x * 256 + threadIdx.x;
    int b = u >> 20;
    int kp = (u >> 12) & 255;
    int p4 = u & 4095;
    const float4 a0 = *(const float4*)(x + ((size_t)b*CC + 2*kp  )*HWW + p4*4);
    const float4 a1 = *(const float4*)(x + ((size_t)b*CC + 2*kp+1)*HWW + p4*4);
    uint4 hi, lo;
    split_pack(a0.x, a1.x, hi.x, lo.x);
    split_pack(a0.y, a1.y, hi.y, lo.y);
    split_pack(a0.z, a1.z, hi.z, lo.z);
    split_pack(a0.w, a1.w, hi.w, lo.w);
    size_t o = (((size_t)b*256 + kp)*HWW) + p4*4;
    *(uint4*)(g_xp_h + o) = hi;
    *(uint4*)(g_xp_l + o) = lo;
}

__global__ void __launch_bounds__(256) pack_W_kernel(const float* __restrict__ Wq,
                                                     const float* __restrict__ Wk,
                                                     const float* __restrict__ Wv)
{
    int u = blockIdx.x * 256 + threadIdx.x;
    if (u >= 256*160) return;
    int kp = u / 160;
    int m4 = u - kp*160;
    int m = m4*4;
    int c0 = 2*kp, c1 = 2*kp+1;
    float v0[4], v1[4];
    #pragma unroll
    for (int j = 0; j < 4; j++) {
        int mm = m + j;
        if (mm < 64)       { v0[j] = Wq[(size_t)c0*DQ + mm];       v1[j] = Wq[(size_t)c1*DQ + mm]; }
        else if (mm < 128) { v0[j] = Wk[(size_t)c0*DQ + mm-64];    v1[j] = Wk[(size_t)c1*DQ + mm-64]; }
        else               { v0[j] = Wv[(size_t)c0*CC + mm-128];   v1[j] = Wv[(size_t)c1*CC + mm-128]; }
    }
    uint4 hi, lo;
    split_pack(v0[0], v1[0], hi.x, lo.x);
    split_pack(v0[1], v1[1], hi.y, lo.y);
    split_pack(v0[2], v1[2], hi.z, lo.z);
    split_pack(v0[3], v1[3], hi.w, lo.w);
    *(uint4*)(g_Wp_h + (size_t)kp*640 + m) = hi;
    *(uint4*)(g_Wp_l + (size_t)kp*640 + m) = lo;
}

// ---------------- HMMA projection GEMM (validated R3) ----------------
__global__ void __launch_bounds__(256) mma_proj_kernel(
    const float* __restrict__ bq, const float* __restrict__ bk, const float* __restrict__ bvv)
{
    __shared__ uint32_t sAh[16][136], sAl[16][136], sBh[16][136], sBl[16][136];

    const int tid = threadIdx.x;
    const int wid = tid >> 5, lane = tid & 31;
    const int gid = lane >> 2, tig = lane & 3;
    const int wm0 = (wid >> 2) * 64;
    const int wn0 = (wid & 3) * 32;
    const int mTile = blockIdx.x * 128;
    const int nTile = blockIdx.y * 128;
    const int b = blockIdx.z;

    float acc[4][4][4];
    #pragma unroll
    for (int i = 0; i < 4; i++)
        #pragma unroll
        for (int j = 0; j < 4; j++)
            #pragma unroll
            for (int r = 0; r < 4; r++) acc[i][j][r] = 0.f;

    const size_t xBase = ((size_t)b*256)*HWW + nTile;

    for (int it = 0; it < 16; ++it) {
        const int kp0 = it * 16;
        #pragma unroll
        for (int i = 0; i < 2; i++) {
            int f = tid + i*256;
            int kp = f >> 5, c4 = (f & 31) * 4;
            *(uint4*)&sAh[kp][c4] = *(const uint4*)&g_Wp_h[(size_t)(kp0+kp)*640 + mTile + c4];
            *(uint4*)&sAl[kp][c4] = *(const uint4*)&g_Wp_l[(size_t)(kp0+kp)*640 + mTile + c4];
            *(uint4*)&sBh[kp][c4] = *(const uint4*)&g_xp_h[xBase + (size_t)(kp0+kp)*HWW + c4];
            *(uint4*)&sBl[kp][c4] = *(const uint4*)&g_xp_l[xBase + (size_t)(kp0+kp)*HWW + c4];
        }
        __syncthreads();
        #pragma unroll
        for (int ks = 0; ks < 2; ks++) {
            const int kb = ks * 8;
            uint32_t ah[4][4], al[4][4], bh[4][2], bl[4][2];
            #pragma unroll
            for (int mi = 0; mi < 4; mi++) {
                int m = wm0 + mi*16 + gid;
                ah[mi][0] = sAh[kb+tig  ][m];
                ah[mi][1] = sAh[kb+tig  ][m+8];
                ah[mi][2] = sAh[kb+tig+4][m];
                ah[mi][3] = sAh[kb+tig+4][m+8];
                al[mi][0] = sAl[kb+tig  ][m];
                al[mi][1] = sAl[kb+tig  ][m+8];
                al[mi][2] = sAl[kb+tig+4][m];
                al[mi][3] = sAl[kb+tig+4][m+8];
            }
            #pragma unroll
            for (int nj = 0; nj < 4; nj++) {
                int n = wn0 + nj*8 + gid;
                bh[nj][0] = sBh[kb+tig  ][n];
                bh[nj][1] = sBh[kb+tig+4][n];
                bl[nj][0] = sBl[kb+tig  ][n];
                bl[nj][1] = sBl[kb+tig+4][n];
            }
            #pragma unroll
            for (int mi = 0; mi < 4; mi++)
                #pragma unroll
                for (int nj = 0; nj < 4; nj++) {
                    mma_bf16(acc[mi][nj], ah[mi], bh[nj]);
                    mma_bf16(acc[mi][nj], ah[mi], bl[nj]);
                    mma_bf16(acc[mi][nj], al[mi], bh[nj]);
                }
        }
        __syncthreads();
    }

    #pragma unroll
    for (int mi = 0; mi < 4; mi++) {
        int rows[2];
        rows[0] = mTile + wm0 + mi*16 + gid;
        rows[1] = rows[0] + 8;
        #pragma unroll
        for (int half = 0; half < 2; half++) {
            int row = rows[half];
            float bias; float* optr;
            if (row < 64)       { bias = bq[row];      optr = g_q + ((size_t)b*DQ + row)      *HWW; }
            else if (row < 128) { bias = bk[row-64];   optr = g_k + ((size_t)b*DQ + (row-64)) *HWW; }
            else                { bias = bvv[row-128]; optr = g_v + ((size_t)b*CC + (row-128))*HWW; }
            #pragma unroll
            for (int nj = 0; nj < 4; nj++) {
                int col = nTile + wn0 + nj*8 + 2*tig;
                float2 f2;
                f2.x = acc[mi][nj][half*2+0] + bias;
                f2.y = acc[mi][nj][half*2+1] + bias;
                *(float2*)(optr + col) = f2;
            }
        }
    }
}

// ---------------- transpose [B,D,H,W] -> [B,W,D,H] (validated) ----------------
__device__ __forceinline__ void transpose_body(const float* __restrict__ src,
                                               float* __restrict__ dst, int D)
{
    __shared__ float t[32][33];
    int bd = blockIdx.z;
    int b = bd / D, d = bd - b*D;
    int w0 = blockIdx.x*32, h0 = blockIdx.y*32;
    const float* s = src + (size_t)bd*HWW;
    int tx = threadIdx.x, ty = threadIdx.y;
    #pragma unroll
    for (int k = 0; k < 32; k += 8)
        t[ty+k][tx] = s[(size_t)(h0+ty+k)*WW + w0 + tx];
    __syncthreads();
    #pragma unroll
    for (int k = 0; k < 32; k += 8) {
        int w = w0 + ty + k;
        int h = h0 + tx;
        dst[(((size_t)b*WW + w)*D + d)*HH + h] = t[tx][ty+k];
    }
}
__global__ void transpose_q_kernel(){ transpose_body(g_q, g_qT, DQ); }
__global__ void transpose_k_kernel(){ transpose_body(g_k, g_kT, DQ); }
__global__ void transpose_v_kernel(){ transpose_body(g_v, g_vT, CC); }

// ---------------- energy (validated) ----------------
template<int MASK>
__device__ __forceinline__ void energy_body(const float* __restrict__ qg,
                                            const float* __restrict__ kg,
                                            float* __restrict__ eg,
                                            long strideB, long strideS, int S1, long cStride)
{
    int s = blockIdx.x;
    int sb = s / S1, ss = s - sb*S1;
    long base = (long)sb*strideB + (long)ss*strideS;
    const float* q = qg + base;
    const float* k = kg + base;
    float* E = eg + (size_t)s * (HH*WW);

    __shared__ float sQ[32][128];
    __shared__ float sK[32][128];
    int tid = threadIdx.x;
    int tx = tid & 15, ty = tid >> 4;
    float acc[8][8] = {};
    for (int c0 = 0; c0 < DQ; c0 += 32) {
        #pragma unroll
        for (int i = 0; i < 16; i++) {
            int e = tid + i*256;
            int cc = e >> 7, ii = e & 127;
            sQ[cc][ii] = q[(size_t)(c0+cc)*cStride + ii];
            sK[cc][ii] = k[(size_t)(c0+cc)*cStride + ii];
        }
        __syncthreads();
        #pragma unroll
        for (int cc = 0; cc < 32; cc++) {
            float a[8], bb[8];
            #pragma unroll
            for (int i = 0; i < 8; i++) a[i]  = sQ[cc][ty + i*16];
            #pragma unroll
            for (int j = 0; j < 8; j++) bb[j] = sK[cc][tx + j*16];
            #pragma unroll
            for (int i = 0; i < 8; i++)
                #pragma unroll
                for (int j = 0; j < 8; j++)
                    acc[i][j] += a[i]*bb[j];
        }
        __syncthreads();
    }
    #pragma unroll
    for (int i = 0; i < 8; i++) {
        int ii = ty + i*16;
        #pragma unroll
        for (int j = 0; j < 8; j++) {
            int jj = tx + j*16;
            float v = acc[i][j];
            if (MASK && ii == jj) v = __int_as_float(0xff800000);
            E[ii*128 + jj] = v;
        }
    }
}
__global__ void __launch_bounds__(256) energy_H_kernel(){
    energy_body<1>(g_qT, g_kT, g_eH, (long)WW*DQ*HH, (long)DQ*HH, WW, HH);
}
__global__ void __launch_bounds__(256) energy_W_kernel(){
    energy_body<0>(g_q,  g_k,  g_eW, (long)DQ*HWW, (long)WW, HH, HWW);
}

// ---------------- softmax (validated R3: in-place fp32) ----------------
__global__ void __launch_bounds__(256) softmax_kernel()
{
    int gwarp = blockIdx.x * 8 + (threadIdx.x >> 5);
    int lane = threadIdx.x & 31;
    int b = gwarp >> 14;
    int rem = gwarp & 16383;
    int h = rem >> 7, w = rem & 127;
    float4* pH = (float4*)(g_eH + (((size_t)b*WW + w)*HH + h)*HH) + lane;
    float4* pW = (float4*)(g_eW + (((size_t)b*HH + h)*WW + w)*WW) + lane;
    float4 vH = *pH, vW = *pW;
    float m = fmaxf(fmaxf(fmaxf(vH.x,vH.y), fmaxf(vH.z,vH.w)),
                    fmaxf(fmaxf(vW.x,vW.y), fmaxf(vW.z,vW.w)));
    #pragma unroll
    for (int o = 16; o > 0; o >>= 1) m = fmaxf(m, __shfl_xor_sync(0xffffffffu, m, o));
    vH.x = __expf(vH.x-m); vH.y = __expf(vH.y-m); vH.z = __expf(vH.z-m); vH.w = __expf(vH.w-m);
    vW.x = __expf(vW.x-m); vW.y = __expf(vW.y-m); vW.z = __expf(vW.z-m); vW.w = __expf(vW.w-m);
    float ssum = (vH.x+vH.y)+(vH.z+vH.w)+(vW.x+vW.y)+(vW.z+vW.w);
    #pragma unroll
    for (int o = 16; o > 0; o >>= 1) ssum += __shfl_xor_sync(0xffffffffu, ssum, o);
    float inv = 1.0f/ssum;
    vH.x*=inv; vH.y*=inv; vH.z*=inv; vH.w*=inv;
    vW.x*=inv; vW.y*=inv; vW.z*=inv; vW.w*=inv;
    *pH = vH; *pW = vW;
}

// ---------------- att pack: fp32 [S][128r][128k] -> K-major packed [S][kp64][r128] ----
__device__ __forceinline__ void att_pack_body(const float* __restrict__ src,
                                              uint32_t* __restrict__ dh,
                                              uint32_t* __restrict__ dl)
{
    __shared__ float t[32][33];
    int s = blockIdx.z;
    int r0 = blockIdx.x*32, k0 = blockIdx.y*32;
    const float* S = src + (size_t)s*16384;
    int tx = threadIdx.x, ty = threadIdx.y;
    #pragma unroll
    for (int j = 0; j < 32; j += 8)
        t[ty+j][tx] = S[(size_t)(r0+ty+j)*128 + k0 + tx];   // t[r_local][k_local]
    __syncthreads();
    #pragma unroll
    for (int j = 0; j < 16; j += 8) {
        int kp = ty + j;
        int rl = tx;
        uint32_t hi, lo;
        split_pack(t[rl][2*kp], t[rl][2*kp+1], hi, lo);
        size_t o = ((size_t)s*64 + (k0>>1) + kp)*128 + r0 + rl;
        dh[o] = hi; dl[o] = lo;
    }
}
__global__ void att_pack_H_kernel(){ att_pack_body(g_eH, g_aHkm_h, g_aHkm_l); }
__global__ void att_pack_W_kernel(){ att_pack_body(g_eW, g_aWkm_h, g_aWkm_l); }

// ---------------- v pack: fp32 [rows=c][k] per slice -> K-major packed [S][kp64][c512] ----
__device__ __forceinline__ void v_pack_body(const float* __restrict__ src,
                                            uint32_t* __restrict__ dh,
                                            uint32_t* __restrict__ dl,
                                            long sB, long sS, long sRow, int S1)
{
    __shared__ float t[32][33];
    int s = blockIdx.z;
    int b = s / S1, ss = s - b*S1;
    const float* S = src + (size_t)b*sB + (size_t)ss*sS;
    int c0 = blockIdx.x*32, k0 = blockIdx.y*32;
    int tx = threadIdx.x, ty = threadIdx.y;
    #pragma unroll
    for (int j = 0; j < 32; j += 8)
        t[ty+j][tx] = S[(size_t)(c0+ty+j)*sRow + k0 + tx];  // t[c_local][k_local]
    __syncthreads();
    #pragma unroll
    for (int j = 0; j < 16; j += 8) {
        int kp = ty + j;
        int cl = tx;
        uint32_t hi, lo;
        split_pack(t[cl][2*kp], t[cl][2*kp+1], hi, lo);
        size_t o = ((size_t)s*64 + (k0>>1) + kp)*512 + c0 + cl;
        dh[o] = hi; dl[o] = lo;
    }
}
__global__ void v_pack_W_kernel(){
    v_pack_body(g_v,  g_vWkm_h, g_vWkm_l, (long)CC*HWW,   (long)WW,    (long)HWW, HH);
}
__global__ void v_pack_H_kernel(){
    v_pack_body(g_vT, g_vHkm_h, g_vHkm_l, (long)WW*CC*HH, (long)CC*HH, (long)HH,  WW);
}

// ---------------- HMMA aggregation (structural clone of mma_proj) ----------------
__device__ __forceinline__ void agg_mma_body(
    const uint32_t* __restrict__ Vh, const uint32_t* __restrict__ Vl,
    const uint32_t* __restrict__ Ah, const uint32_t* __restrict__ Al,
    float* __restrict__ O, long oB, long oS, long oRow)
{
    __shared__ uint32_t sAh[16][136], sAl[16][136], sBh[16][136], sBl[16][136];

    const int tid = threadIdx.x;
    const int wid = tid >> 5, lane = tid & 31;
    const int gid = lane >> 2, tig = lane & 3;
    const int wm0 = (wid >> 2) * 64;
    const int wn0 = (wid & 3) * 32;
    const int mTile = blockIdx.x * 128;
    const int s = blockIdx.z;
    const int b = s >> 7, ss = s & 127;

    const uint32_t* Vh_s = Vh + (size_t)s*64*512 + mTile;
    const uint32_t* Vl_s = Vl + (size_t)s*64*512 + mTile;
    const uint32_t* Ah_s = Ah + (size_t)s*64*128;
    const uint32_t* Al_s = Al + (size_t)s*64*128;
    float* O_s = O + (size_t)b*oB + (size_t)ss*oS + (size_t)mTile*oRow;

    float acc[4][4][4];
    #pragma unroll
    for (int i = 0; i < 4; i++)
        #pragma unroll
        for (int j = 0; j < 4; j++)
            #pragma unroll
            for (int r = 0; r < 4; r++) acc[i][j][r] = 0.f;

    for (int ch = 0; ch < 4; ++ch) {
        const int kp0 = ch * 16;
        #pragma unroll
        for (int i = 0; i < 2; i++) {
            int f = tid + i*256;
            int kp = f >> 5, c4 = (f & 31) * 4;
            *(uint4*)&sAh[kp][c4] = *(const uint4*)(Vh_s + (size_t)(kp0+kp)*512 + c4);
            *(uint4*)&sAl[kp][c4] = *(const uint4*)(Vl_s + (size_t)(kp0+kp)*512 + c4);
            *(uint4*)&sBh[kp][c4] = *(const uint4*)(Ah_s + (size_t)(kp0+kp)*128 + c4);
            *(uint4*)&sBl[kp][c4] = *(const uint4*)(Al_s + (size_t)(kp0+kp)*128 + c4);
        }
        __syncthreads();
        #pragma unroll
        for (int ks = 0; ks < 2; ks++) {
            const int kb = ks * 8;
            uint32_t ah[4][4], al[4][4], bh[4][2], bl[4][2];
            #pragma unroll
            for (int mi = 0; mi < 4; mi++) {
                int m = wm0 + mi*16 + gid;
                ah[mi][0] = sAh[kb+tig  ][m];
                ah[mi][1] = sAh[kb+tig  ][m+8];
                ah[mi][2] = sAh[kb+tig+4][m];
                ah[mi][3] = sAh[kb+tig+4][m+8];
                al[mi][0] = sAl[kb+tig  ][m];
                al[mi][1] = sAl[kb+tig  ][m+8];
                al[mi][2] = sAl[kb+tig+4][m];
                al[mi][3] = sAl[kb+tig+4][m+8];
            }
            #pragma unroll
            for (int nj = 0; nj < 4; nj++) {
                int n = wn0 + nj*8 + gid;
                bh[nj][0] = sBh[kb+tig  ][n];
                bh[nj][1] = sBh[kb+tig+4][n];
                bl[nj][0] = sBl[kb+tig  ][n];
                bl[nj][1] = sBl[kb+tig+4][n];
            }
            #pragma unroll
            for (int mi = 0; mi < 4; mi++)
                #pragma unroll
                for (int nj = 0; nj < 4; nj++) {
                    mma_bf16(acc[mi][nj], ah[mi], bh[nj]);
                    mma_bf16(acc[mi][nj], ah[mi], bl[nj]);
                    mma_bf16(acc[mi][nj], al[mi], bh[nj]);
                }
        }
        __syncthreads();
    }

    #pragma unroll
    for (int mi = 0; mi < 4; mi++) {
        #pragma unroll
        for (int half = 0; half < 2; half++) {
            int rowL = wm0 + mi*16 + gid + half*8;
            float* optr = O_s + (size_t)rowL*oRow;
            #pragma unroll
            for (int nj = 0; nj < 4; nj++) {
                int col = wn0 + nj*8 + 2*tig;
                float2 f2;
                f2.x = acc[mi][nj][half*2+0];
                f2.y = acc[mi][nj][half*2+1];
                *(float2*)(optr + col) = f2;
            }
        }
    }
}
__global__ void __launch_bounds__(256) agg_H_mma_kernel(){
    // slice (b,w): O[c,h] -> g_oH[b][w][c][h]
    agg_mma_body(g_vHkm_h, g_vHkm_l, g_aHkm_h, g_aHkm_l, g_oH,
                 (long)WW*CC*HH, (long)CC*HH, (long)HH);
}
__global__ void __launch_bounds__(256) agg_W_mma_kernel(float* __restrict__ out){
    // slice (b,h): O[c,w] -> out[b][c][h][w]   (out = harness pointer, valid as arg)
    agg_mma_body(g_vWkm_h, g_vWkm_l, g_aWkm_h, g_aWkm_l, out,
                 (long)CC*HWW, (long)WW, (long)HWW);
}

// ---------------- combine: out = GAMMA*(out_H^T + out_W) + x ----------------
__global__ void combine_kernel(const float* __restrict__ x, float* __restrict__ out)
{
    __shared__ float t[32][33];
    int bc = blockIdx.z;
    int b = bc >> 9, c = bc & 511;
    int w0 = blockIdx.x*32, h0 = blockIdx.y*32;
    int tx = threadIdx.x, ty = threadIdx.y;
    #pragma unroll
    for (int k = 0; k < 32; k += 8) {
        int w = w0 + ty + k;
        int h = h0 + tx;
        t[ty+k][tx] = g_oH[(((size_t)b*WW + w)*CC + c)*HH + h];
    }
    __syncthreads();
    #pragma unroll
    for (int k = 0; k < 32; k += 8) {
        int h = h0 + ty + k;
        int w = w0 + tx;
        size_t idx = ((size_t)bc*HH + h)*WW + w;
        out[idx] = GAMMA_*(t[tx][ty+k] + out[idx]) + x[idx];
    }
}

// ---------------- launch ----------------
extern "C" void kernel_launch(void* const* d_in, const int* in_sizes, int n_in,
                              void* d_out, int out_size)
{
    const float* x  = (const float*)d_in[0];
    const float* Wq = (const float*)d_in[1];
    const float* bq = (const float*)d_in[2];
    const float* Wk = (const float*)d_in[3];
    const float* bk = (const float*)d_in[4];
    const float* Wv = (const float*)d_in[5];
    const float* bv = (const float*)d_in[6];
    float* out = (float*)d_out;

    dim3 tb(32, 8);

    pack_W_kernel<<<160, 256>>>(Wq, Wk, Wv);
    pack_x_kernel<<<(BB*256*HWW/4)/256, 256>>>(x);

    mma_proj_kernel<<<dim3(5, HWW/128, BB), 256>>>(bq, bk, bv);

    transpose_q_kernel<<<dim3(WW/32, HH/32, BB*DQ), tb>>>();
    transpose_k_kernel<<<dim3(WW/32, HH/32, BB*DQ), tb>>>();
    transpose_v_kernel<<<dim3(WW/32, HH/32, BB*CC), tb>>>();

    energy_H_kernel<<<BB*WW, 256>>>();
    energy_W_kernel<<<BB*HH, 256>>>();

    softmax_kernel<<<(BB*HH*WW)/8, 256>>>();

    att_pack_H_kernel<<<dim3(4, 4, BB*WW), tb>>>();
    att_pack_W_kernel<<<dim3(4, 4, BB*HH), tb>>>();
    v_pack_W_kernel<<<dim3(16, 4, BB*HH), tb>>>();
    v_pack_H_kernel<<<dim3(16, 4, BB*WW), tb>>>();

    agg_H_mma_kernel<<<dim3(4, 1, BB*WW), 256>>>();
    agg_W_mma_kernel<<<dim3(4, 1, BB*HH), 256>>>(out);

    combine_kernel<<<dim3(WW/32, HH/32, BB*CC), tb>>>(x, out);
}

// round 8
// speedup vs baseline: 2.5558x; 1.0740x over previous
#include <cuda_runtime.h>
#include <cuda_bf16.h>
#include <cstdint>

#define BB 8
#define CC 512
#define DQ 64
#define HH 128
#define WW 128
#define HWW 16384
#define GAMMA_ 1.0f

// ---------------- scratch (device globals; no allocation) ----------------
__device__ float g_q [BB*DQ*HWW];        // [B,DQ,H,W]
__device__ float g_k [BB*DQ*HWW];        // [B,DQ,H,W]
__device__ float g_v [BB*CC*HWW];        // [B,C ,H,W]
__device__ float g_eH[BB*WW*HH*HH];      // [B,W,H,G]  raw energies
__device__ float g_eW[BB*HH*WW*WW];      // [B,H,W,V]  raw energies
__device__ float g_oH[BB*WW*CC*HH];      // [B,W,C,H]
__device__ float2 g_stat[BB*HWW];        // per-pixel (max, 1/sum)

// packed bf16 hi/lo (uint32 = two consecutive-K bf16, low half = even k)
__device__ uint32_t g_xp_h[(size_t)BB*256*HWW];    // [b][kp][p]
__device__ uint32_t g_xp_l[(size_t)BB*256*HWW];
__device__ uint32_t g_Wp_h[256*640];               // [kp][m]
__device__ uint32_t g_Wp_l[256*640];
// K-major operands for aggregation ([slice][kp=64][cols])
__device__ uint32_t g_vWkm_h[(size_t)BB*HH*64*512]; // [b*HH+h][wp][c]
__device__ uint32_t g_vWkm_l[(size_t)BB*HH*64*512];
__device__ uint32_t g_vHkm_h[(size_t)BB*WW*64*512]; // [b*WW+w][hp][c]
__device__ uint32_t g_vHkm_l[(size_t)BB*WW*64*512];
__device__ uint32_t g_aHkm_h[(size_t)BB*WW*64*128]; // [b*WW+w][gp][h]
__device__ uint32_t g_aHkm_l[(size_t)BB*WW*64*128];
__device__ uint32_t g_aWkm_h[(size_t)BB*HH*64*128]; // [b*HH+h][vp][w]
__device__ uint32_t g_aWkm_l[(size_t)BB*HH*64*128];
// K-major operands for energy ([slice][kp=32][128])
__device__ uint32_t g_qWkm_h[(size_t)BB*HH*32*128]; // [b*HH+h][dp][w]
__device__ uint32_t g_qWkm_l[(size_t)BB*HH*32*128];
__device__ uint32_t g_kWkm_h[(size_t)BB*HH*32*128];
__device__ uint32_t g_kWkm_l[(size_t)BB*HH*32*128];
__device__ uint32_t g_qHkm_h[(size_t)BB*WW*32*128]; // [b*WW+w][dp][h]
__device__ uint32_t g_qHkm_l[(size_t)BB*WW*32*128];
__device__ uint32_t g_kHkm_h[(size_t)BB*WW*32*128];
__device__ uint32_t g_kHkm_l[(size_t)BB*WW*32*128];

// ---------------- helpers ----------------
__device__ __forceinline__ void split_pack(float v0, float v1, uint32_t& hi, uint32_t& lo){
    __nv_bfloat16 h0 = __float2bfloat16(v0);
    __nv_bfloat16 h1 = __float2bfloat16(v1);
    __nv_bfloat16 l0 = __float2bfloat16(v0 - __bfloat162float(h0));
    __nv_bfloat16 l1 = __float2bfloat16(v1 - __bfloat162float(h1));
    hi = ((uint32_t)__bfloat16_as_ushort(h1) << 16) | (uint32_t)__bfloat16_as_ushort(h0);
    lo = ((uint32_t)__bfloat16_as_ushort(l1) << 16) | (uint32_t)__bfloat16_as_ushort(l0);
}

__device__ __forceinline__ void mma_bf16(float* c, const uint32_t* a, const uint32_t* b){
    asm volatile("mma.sync.aligned.m16n8k16.row.col.f32.bf16.bf16.f32 "
        "{%0,%1,%2,%3}, {%4,%5,%6,%7}, {%8,%9}, {%0,%1,%2,%3};"
        : "+f"(c[0]), "+f"(c[1]), "+f"(c[2]), "+f"(c[3])
        : "r"(a[0]), "r"(a[1]), "r"(a[2]), "r"(a[3]), "r"(b[0]), "r"(b[1]));
}

// ---------------- pack kernels (x, W) ----------------
__global__ void __launch_bounds__(256) pack_x_kernel(const float* __restrict__ x)
{
    int u = blockIdx.x * 256 + threadIdx.x;
    int b = u >> 20;
    int kp = (u >> 12) & 255;
    int p4 = u & 4095;
    const float4 a0 = *(const float4*)(x + ((size_t)b*CC + 2*kp  )*HWW + p4*4);
    const float4 a1 = *(const float4*)(x + ((size_t)b*CC + 2*kp+1)*HWW + p4*4);
    uint4 hi, lo;
    split_pack(a0.x, a1.x, hi.x, lo.x);
    split_pack(a0.y, a1.y, hi.y, lo.y);
    split_pack(a0.z, a1.z, hi.z, lo.z);
    split_pack(a0.w, a1.w, hi.w, lo.w);
    size_t o = (((size_t)b*256 + kp)*HWW) + p4*4;
    *(uint4*)(g_xp_h + o) = hi;
    *(uint4*)(g_xp_l + o) = lo;
}

__global__ void __launch_bounds__(256) pack_W_kernel(const float* __restrict__ Wq,
                                                     const float* __restrict__ Wk,
                                                     const float* __restrict__ Wv)
{
    int u = blockIdx.x * 256 + threadIdx.x;
    if (u >= 256*160) return;
    int kp = u / 160;
    int m4 = u - kp*160;
    int m = m4*4;
    int c0 = 2*kp, c1 = 2*kp+1;
    float v0[4], v1[4];
    #pragma unroll
    for (int j = 0; j < 4; j++) {
        int mm = m + j;
        if (mm < 64)       { v0[j] = Wq[(size_t)c0*DQ + mm];       v1[j] = Wq[(size_t)c1*DQ + mm]; }
        else if (mm < 128) { v0[j] = Wk[(size_t)c0*DQ + mm-64];    v1[j] = Wk[(size_t)c1*DQ + mm-64]; }
        else               { v0[j] = Wv[(size_t)c0*CC + mm-128];   v1[j] = Wv[(size_t)c1*CC + mm-128]; }
    }
    uint4 hi, lo;
    split_pack(v0[0], v1[0], hi.x, lo.x);
    split_pack(v0[1], v1[1], hi.y, lo.y);
    split_pack(v0[2], v1[2], hi.z, lo.z);
    split_pack(v0[3], v1[3], hi.w, lo.w);
    *(uint4*)(g_Wp_h + (size_t)kp*640 + m) = hi;
    *(uint4*)(g_Wp_l + (size_t)kp*640 + m) = lo;
}

// ---------------- HMMA projection GEMM (validated) ----------------
__global__ void __launch_bounds__(256) mma_proj_kernel(
    const float* __restrict__ bq, const float* __restrict__ bk, const float* __restrict__ bvv)
{
    __shared__ uint32_t sAh[16][136], sAl[16][136], sBh[16][136], sBl[16][136];

    const int tid = threadIdx.x;
    const int wid = tid >> 5, lane = tid & 31;
    const int gid = lane >> 2, tig = lane & 3;
    const int wm0 = (wid >> 2) * 64;
    const int wn0 = (wid & 3) * 32;
    const int mTile = blockIdx.x * 128;
    const int nTile = blockIdx.y * 128;
    const int b = blockIdx.z;

    float acc[4][4][4];
    #pragma unroll
    for (int i = 0; i < 4; i++)
        #pragma unroll
        for (int j = 0; j < 4; j++)
            #pragma unroll
            for (int r = 0; r < 4; r++) acc[i][j][r] = 0.f;

    const size_t xBase = ((size_t)b*256)*HWW + nTile;

    for (int it = 0; it < 16; ++it) {
        const int kp0 = it * 16;
        #pragma unroll
        for (int i = 0; i < 2; i++) {
            int f = tid + i*256;
            int kp = f >> 5, c4 = (f & 31) * 4;
            *(uint4*)&sAh[kp][c4] = *(const uint4*)&g_Wp_h[(size_t)(kp0+kp)*640 + mTile + c4];
            *(uint4*)&sAl[kp][c4] = *(const uint4*)&g_Wp_l[(size_t)(kp0+kp)*640 + mTile + c4];
            *(uint4*)&sBh[kp][c4] = *(const uint4*)&g_xp_h[xBase + (size_t)(kp0+kp)*HWW + c4];
            *(uint4*)&sBl[kp][c4] = *(const uint4*)&g_xp_l[xBase + (size_t)(kp0+kp)*HWW + c4];
        }
        __syncthreads();
        #pragma unroll
        for (int ks = 0; ks < 2; ks++) {
            const int kb = ks * 8;
            uint32_t ah[4][4], al[4][4], bh[4][2], bl[4][2];
            #pragma unroll
            for (int mi = 0; mi < 4; mi++) {
                int m = wm0 + mi*16 + gid;
                ah[mi][0] = sAh[kb+tig  ][m];
                ah[mi][1] = sAh[kb+tig  ][m+8];
                ah[mi][2] = sAh[kb+tig+4][m];
                ah[mi][3] = sAh[kb+tig+4][m+8];
                al[mi][0] = sAl[kb+tig  ][m];
                al[mi][1] = sAl[kb+tig  ][m+8];
                al[mi][2] = sAl[kb+tig+4][m];
                al[mi][3] = sAl[kb+tig+4][m+8];
            }
            #pragma unroll
            for (int nj = 0; nj < 4; nj++) {
                int n = wn0 + nj*8 + gid;
                bh[nj][0] = sBh[kb+tig  ][n];
                bh[nj][1] = sBh[kb+tig+4][n];
                bl[nj][0] = sBl[kb+tig  ][n];
                bl[nj][1] = sBl[kb+tig+4][n];
            }
            #pragma unroll
            for (int mi = 0; mi < 4; mi++)
                #pragma unroll
                for (int nj = 0; nj < 4; nj++) {
                    mma_bf16(acc[mi][nj], ah[mi], bh[nj]);
                    mma_bf16(acc[mi][nj], ah[mi], bl[nj]);
                    mma_bf16(acc[mi][nj], al[mi], bh[nj]);
                }
        }
        __syncthreads();
    }

    #pragma unroll
    for (int mi = 0; mi < 4; mi++) {
        int rows[2];
        rows[0] = mTile + wm0 + mi*16 + gid;
        rows[1] = rows[0] + 8;
        #pragma unroll
        for (int half = 0; half < 2; half++) {
            int row = rows[half];
            float bias; float* optr;
            if (row < 64)       { bias = bq[row];      optr = g_q + ((size_t)b*DQ + row)      *HWW; }
            else if (row < 128) { bias = bk[row-64];   optr = g_k + ((size_t)b*DQ + (row-64)) *HWW; }
            else                { bias = bvv[row-128]; optr = g_v + ((size_t)b*CC + (row-128))*HWW; }
            #pragma unroll
            for (int nj = 0; nj < 4; nj++) {
                int col = nTile + wn0 + nj*8 + 2*tig;
                float2 f2;
                f2.x = acc[mi][nj][half*2+0] + bias;
                f2.y = acc[mi][nj][half*2+1] + bias;
                *(float2*)(optr + col) = f2;
            }
        }
    }
}

// ---------------- packA: K along rows, cols contiguous (q/k -> W-orientation) ----
// out[(b*HH+h)][dp][w] from src[b][d][h][w]; tile [d32][w32] fixed (b,h)
__device__ __forceinline__ void packA_body(const float* __restrict__ src,
                                           uint32_t* __restrict__ dh,
                                           uint32_t* __restrict__ dl)
{
    __shared__ float t[32][33];
    int s = blockIdx.z;                 // b*HH + h
    int b = s >> 7, h = s & 127;
    int w0 = blockIdx.x*32, d0 = blockIdx.y*32;
    int tx = threadIdx.x, ty = threadIdx.y;
    const float* S = src + (size_t)b*DQ*HWW + (size_t)h*WW;
    #pragma unroll
    for (int j = 0; j < 32; j += 8)
        t[ty+j][tx] = S[(size_t)(d0+ty+j)*HWW + w0 + tx];   // t[d_local][w_local]
    __syncthreads();
    #pragma unroll
    for (int j = 0; j < 16; j += 8) {
        int kp = ty + j;
        uint32_t hi, lo;
        split_pack(t[2*kp][tx], t[2*kp+1][tx], hi, lo);
        size_t o = ((size_t)s*32 + (d0>>1) + kp)*128 + w0 + tx;
        dh[o] = hi; dl[o] = lo;
    }
}
__global__ void packA_q_kernel(){ packA_body(g_q, g_qWkm_h, g_qWkm_l); }
__global__ void packA_k_kernel(){ packA_body(g_k, g_kWkm_h, g_kWkm_l); }

// ---------------- packB: K along d, cols h, slices w (q/k -> H-orientation) ----
// out[(b*WW+w)][dp][h] from src[b][d][h][w]; chunk [d8][h32][w32]
__device__ __forceinline__ void packB_body(const float* __restrict__ src,
                                           uint32_t* __restrict__ dh,
                                           uint32_t* __restrict__ dl)
{
    __shared__ float t[8][32][33];
    int z = blockIdx.z;                 // b*8 + d8
    int b = z >> 3, d0 = (z & 7) * 8;
    int w0 = blockIdx.x*32, h0 = blockIdx.y*32;
    int tid = threadIdx.x;
    int tx = tid & 31, ty = tid >> 5;
    #pragma unroll
    for (int dd = 0; dd < 8; dd++)
        #pragma unroll
        for (int j = 0; j < 32; j += 8)
            t[dd][ty+j][tx] = src[((size_t)b*DQ + d0+dd)*HWW + (size_t)(h0+ty+j)*WW + w0 + tx];
    __syncthreads();
    #pragma unroll
    for (int it = 0; it < 16; it++) {
        int idx = tid + it*256;
        int hl = idx & 31, wl = (idx >> 5) & 31, dpl = idx >> 10;
        uint32_t hi, lo;
        split_pack(t[2*dpl][hl][wl], t[2*dpl+1][hl][wl], hi, lo);
        size_t o = (((size_t)b*WW + w0 + wl)*32 + (d0>>1) + dpl)*128 + h0 + hl;
        dh[o] = hi; dl[o] = lo;
    }
}
__global__ void __launch_bounds__(256) packB_q_kernel(){ packB_body(g_q, g_qHkm_h, g_qHkm_l); }
__global__ void __launch_bounds__(256) packB_k_kernel(){ packB_body(g_k, g_kHkm_h, g_kHkm_l); }

// ---------------- v pack W-orientation (validated R6) ----------------
// out[(b*HH+h)][wp][c] from g_v; rows c (stride HWW), k = w contiguous
__device__ __forceinline__ void v_pack_body(const float* __restrict__ src,
                                            uint32_t* __restrict__ dh,
                                            uint32_t* __restrict__ dl,
                                            long sB, long sS, long sRow, int S1)
{
    __shared__ float t[32][33];
    int s = blockIdx.z;
    int b = s / S1, ss = s - b*S1;
    const float* S = src + (size_t)b*sB + (size_t)ss*sS;
    int c0 = blockIdx.x*32, k0 = blockIdx.y*32;
    int tx = threadIdx.x, ty = threadIdx.y;
    #pragma unroll
    for (int j = 0; j < 32; j += 8)
        t[ty+j][tx] = S[(size_t)(c0+ty+j)*sRow + k0 + tx];
    __syncthreads();
    #pragma unroll
    for (int j = 0; j < 16; j += 8) {
        int kp = ty + j;
        int cl = tx;
        uint32_t hi, lo;
        split_pack(t[cl][2*kp], t[cl][2*kp+1], hi, lo);
        size_t o = ((size_t)s*64 + (k0>>1) + kp)*512 + c0 + cl;
        dh[o] = hi; dl[o] = lo;
    }
}
__global__ void v_pack_W_kernel(){
    v_pack_body(g_v, g_vWkm_h, g_vWkm_l, (long)CC*HWW, (long)WW, (long)HWW, HH);
}

// ---------------- v pack H-orientation: direct from g_v ----------------
// out[(b*WW+w)][hp][c] from g_v[b][c][h][w]; chunk [c32][h8][w32]
__global__ void __launch_bounds__(256) v_packH_kernel()
{
    __shared__ float t[8][32][33];       // [h][c][w]
    int z = blockIdx.z;                  // b*16 + c32tile
    int b = z >> 4, c0 = (z & 15) * 32;
    int w0 = blockIdx.x*32, h0 = blockIdx.y*8;
    int tid = threadIdx.x;
    int tx = tid & 31, ty = tid >> 5;
    #pragma unroll
    for (int hh = 0; hh < 8; hh++)
        #pragma unroll
        for (int j = 0; j < 32; j += 8)
            t[hh][ty+j][tx] = g_v[((size_t)b*CC + c0+ty+j)*HWW + (size_t)(h0+hh)*WW + w0 + tx];
    __syncthreads();
    #pragma unroll
    for (int it = 0; it < 16; it++) {
        int idx = tid + it*256;
        int cl = idx & 31, wl = (idx >> 5) & 31, hpl = idx >> 10;
        uint32_t hi, lo;
        split_pack(t[2*hpl][cl][wl], t[2*hpl+1][cl][wl], hi, lo);
        size_t o = (((size_t)b*WW + w0 + wl)*64 + (h0>>1) + hpl)*512 + c0 + cl;
        g_vHkm_h[o] = hi; g_vHkm_l[o] = lo;
    }
}

// ---------------- HMMA energy GEMM: E[m,n] = sum_d Q[d,m]*K[d,n], K=64 ----------------
template<int MASK>
__device__ __forceinline__ void energy_mma_body(
    const uint32_t* __restrict__ Qh, const uint32_t* __restrict__ Ql,
    const uint32_t* __restrict__ Kh, const uint32_t* __restrict__ Kl,
    float* __restrict__ E)
{
    __shared__ uint32_t sAh[16][136], sAl[16][136], sBh[16][136], sBl[16][136];

    const int tid = threadIdx.x;
    const int wid = tid >> 5, lane = tid & 31;
    const int gid = lane >> 2, tig = lane & 3;
    const int wm0 = (wid >> 2) * 64;
    const int wn0 = (wid & 3) * 32;
    const int s = blockIdx.z;

    const uint32_t* Qh_s = Qh + (size_t)s*32*128;
    const uint32_t* Ql_s = Ql + (size_t)s*32*128;
    const uint32_t* Kh_s = Kh + (size_t)s*32*128;
    const uint32_t* Kl_s = Kl + (size_t)s*32*128;
    float* E_s = E + (size_t)s*16384;

    float acc[4][4][4];
    #pragma unroll
    for (int i = 0; i < 4; i++)
        #pragma unroll
        for (int j = 0; j < 4; j++)
            #pragma unroll
            for (int r = 0; r < 4; r++) acc[i][j][r] = 0.f;

    for (int ch = 0; ch < 2; ++ch) {
        const int kp0 = ch * 16;
        #pragma unroll
        for (int i = 0; i < 2; i++) {
            int f = tid + i*256;
            int kp = f >> 5, c4 = (f & 31) * 4;
            *(uint4*)&sAh[kp][c4] = *(const uint4*)(Qh_s + (size_t)(kp0+kp)*128 + c4);
            *(uint4*)&sAl[kp][c4] = *(const uint4*)(Ql_s + (size_t)(kp0+kp)*128 + c4);
            *(uint4*)&sBh[kp][c4] = *(const uint4*)(Kh_s + (size_t)(kp0+kp)*128 + c4);
            *(uint4*)&sBl[kp][c4] = *(const uint4*)(Kl_s + (size_t)(kp0+kp)*128 + c4);
        }
        __syncthreads();
        #pragma unroll
        for (int ks = 0; ks < 2; ks++) {
            const int kb = ks * 8;
            uint32_t ah[4][4], al[4][4], bh[4][2], bl[4][2];
            #pragma unroll
            for (int mi = 0; mi < 4; mi++) {
                int m = wm0 + mi*16 + gid;
                ah[mi][0] = sAh[kb+tig  ][m];
                ah[mi][1] = sAh[kb+tig  ][m+8];
                ah[mi][2] = sAh[kb+tig+4][m];
                ah[mi][3] = sAh[kb+tig+4][m+8];
                al[mi][0] = sAl[kb+tig  ][m];
                al[mi][1] = sAl[kb+tig  ][m+8];
                al[mi][2] = sAl[kb+tig+4][m];
                al[mi][3] = sAl[kb+tig+4][m+8];
            }
            #pragma unroll
            for (int nj = 0; nj < 4; nj++) {
                int n = wn0 + nj*8 + gid;
                bh[nj][0] = sBh[kb+tig  ][n];
                bh[nj][1] = sBh[kb+tig+4][n];
                bl[nj][0] = sBl[kb+tig  ][n];
                bl[nj][1] = sBl[kb+tig+4][n];
            }
            #pragma unroll
            for (int mi = 0; mi < 4; mi++)
                #pragma unroll
                for (int nj = 0; nj < 4; nj++) {
                    mma_bf16(acc[mi][nj], ah[mi], bh[nj]);
                    mma_bf16(acc[mi][nj], ah[mi], bl[nj]);
                    mma_bf16(acc[mi][nj], al[mi], bh[nj]);
                }
        }
        __syncthreads();
    }

    const float NINF = __int_as_float(0xff800000);
    #pragma unroll
    for (int mi = 0; mi < 4; mi++) {
        #pragma unroll
        for (int half = 0; half < 2; half++) {
            int row = wm0 + mi*16 + gid + half*8;
            #pragma unroll
            for (int nj = 0; nj < 4; nj++) {
                int col = wn0 + nj*8 + 2*tig;
                float2 f2;
                f2.x = acc[mi][nj][half*2+0];
                f2.y = acc[mi][nj][half*2+1];
                if (MASK) {
                    if (row == col)   f2.x = NINF;
                    if (row == col+1) f2.y = NINF;
                }
                *(float2*)(E_s + (size_t)row*128 + col) = f2;
            }
        }
    }
}
__global__ void __launch_bounds__(256) energy_H_mma_kernel(){
    energy_mma_body<1>(g_qHkm_h, g_qHkm_l, g_kHkm_h, g_kHkm_l, g_eH);
}
__global__ void __launch_bounds__(256) energy_W_mma_kernel(){
    energy_mma_body<0>(g_qWkm_h, g_qWkm_l, g_kWkm_h, g_kWkm_l, g_eW);
}

// ---------------- reduce: per-pixel (max, 1/sum) over concat rows ----------------
__global__ void __launch_bounds__(256) reduce_kernel()
{
    int gwarp = blockIdx.x * 8 + (threadIdx.x >> 5);
    int lane = threadIdx.x & 31;
    int b = gwarp >> 14;
    int rem = gwarp & 16383;
    int h = rem >> 7, w = rem & 127;
    const float4* pH = (const float4*)(g_eH + (((size_t)b*WW + w)*HH + h)*HH) + lane;
    const float4* pW = (const float4*)(g_eW + (((size_t)b*HH + h)*WW + w)*WW) + lane;
    float4 vH = *pH, vW = *pW;
    float m = fmaxf(fmaxf(fmaxf(vH.x,vH.y), fmaxf(vH.z,vH.w)),
                    fmaxf(fmaxf(vW.x,vW.y), fmaxf(vW.z,vW.w)));
    #pragma unroll
    for (int o = 16; o > 0; o >>= 1) m = fmaxf(m, __shfl_xor_sync(0xffffffffu, m, o));
    float ssum = __expf(vH.x-m)+__expf(vH.y-m)+__expf(vH.z-m)+__expf(vH.w-m)
               + __expf(vW.x-m)+__expf(vW.y-m)+__expf(vW.z-m)+__expf(vW.w-m);
    #pragma unroll
    for (int o = 16; o > 0; o >>= 1) ssum += __shfl_xor_sync(0xffffffffu, ssum, o);
    if (lane == 0)
        g_stat[(size_t)b*HWW + (size_t)h*WW + w] = make_float2(m, 1.0f/ssum);
}

// ---------------- finalize: raw e -> exp-normalized packed K-major att ----------------
__device__ __forceinline__ void finalize_body(const float* __restrict__ src,
                                              uint32_t* __restrict__ dh,
                                              uint32_t* __restrict__ dl,
                                              size_t statBase, int statStride)
{
    __shared__ float t[32][33];
    int s = blockIdx.z;
    int r0 = blockIdx.x*32, k0 = blockIdx.y*32;
    const float* S = src + (size_t)s*16384;
    int tx = threadIdx.x, ty = threadIdx.y;
    #pragma unroll
    for (int j = 0; j < 32; j += 8)
        t[ty+j][tx] = S[(size_t)(r0+ty+j)*128 + k0 + tx];
    __syncthreads();
    float2 st = g_stat[statBase + (size_t)(r0+tx)*statStride];
    #pragma unroll
    for (int j = 0; j < 16; j += 8) {
        int kp = ty + j;
        float a0 = __expf(t[tx][2*kp  ] - st.x) * st.y;
        float a1 = __expf(t[tx][2*kp+1] - st.x) * st.y;
        uint32_t hi, lo;
        split_pack(a0, a1, hi, lo);
        size_t o = ((size_t)s*64 + (k0>>1) + kp)*128 + r0 + tx;
        dh[o] = hi; dl[o] = lo;
    }
}
__global__ void finalize_H_kernel(){
    int s = blockIdx.z;                // (b, w); rows = h
    int b = s >> 7, w = s & 127;
    finalize_body(g_eH, g_aHkm_h, g_aHkm_l, (size_t)b*HWW + w, WW);
}
__global__ void finalize_W_kernel(){
    int s = blockIdx.z;                // (b, h); rows = w
    int b = s >> 7, h = s & 127;
    finalize_body(g_eW, g_aWkm_h, g_aWkm_l, (size_t)b*HWW + (size_t)h*WW, 1);
}

// ---------------- HMMA aggregation (validated R6) ----------------
__device__ __forceinline__ void agg_mma_body(
    const uint32_t* __restrict__ Vh, const uint32_t* __restrict__ Vl,
    const uint32_t* __restrict__ Ah, const uint32_t* __restrict__ Al,
    float* __restrict__ O, long oB, long oS, long oRow)
{
    __shared__ uint32_t sAh[16][136], sAl[16][136], sBh[16][136], sBl[16][136];

    const int tid = threadIdx.x;
    const int wid = tid >> 5, lane = tid & 31;
    const int gid = lane >> 2, tig = lane & 3;
    const int wm0 = (wid >> 2) * 64;
    const int wn0 = (wid & 3) * 32;
    const int mTile = blockIdx.x * 128;
    const int s = blockIdx.z;
    const int b = s >> 7, ss = s & 127;

    const uint32_t* Vh_s = Vh + (size_t)s*64*512 + mTile;
    const uint32_t* Vl_s = Vl + (size_t)s*64*512 + mTile;
    const uint32_t* Ah_s = Ah + (size_t)s*64*128;
    const uint32_t* Al_s = Al + (size_t)s*64*128;
    float* O_s = O + (size_t)b*oB + (size_t)ss*oS + (size_t)mTile*oRow;

    float acc[4][4][4];
    #pragma unroll
    for (int i = 0; i < 4; i++)
        #pragma unroll
        for (int j = 0; j < 4; j++)
            #pragma unroll
            for (int r = 0; r < 4; r++) acc[i][j][r] = 0.f;

    for (int ch = 0; ch < 4; ++ch) {
        const int kp0 = ch * 16;
        #pragma unroll
        for (int i = 0; i < 2; i++) {
            int f = tid + i*256;
            int kp = f >> 5, c4 = (f & 31) * 4;
            *(uint4*)&sAh[kp][c4] = *(const uint4*)(Vh_s + (size_t)(kp0+kp)*512 + c4);
            *(uint4*)&sAl[kp][c4] = *(const uint4*)(Vl_s + (size_t)(kp0+kp)*512 + c4);
            *(uint4*)&sBh[kp][c4] = *(const uint4*)(Ah_s + (size_t)(kp0+kp)*128 + c4);
            *(uint4*)&sBl[kp][c4] = *(const uint4*)(Al_s + (size_t)(kp0+kp)*128 + c4);
        }
        __syncthreads();
        #pragma unroll
        for (int ks = 0; ks < 2; ks++) {
            const int kb = ks * 8;
            uint32_t ah[4][4], al[4][4], bh[4][2], bl[4][2];
            #pragma unroll
            for (int mi = 0; mi < 4; mi++) {
                int m = wm0 + mi*16 + gid;
                ah[mi][0] = sAh[kb+tig  ][m];
                ah[mi][1] = sAh[kb+tig  ][m+8];
                ah[mi][2] = sAh[kb+tig+4][m];
                ah[mi][3] = sAh[kb+tig+4][m+8];
                al[mi][0] = sAl[kb+tig  ][m];
                al[mi][1] = sAl[kb+tig  ][m+8];
                al[mi][2] = sAl[kb+tig+4][m];
                al[mi][3] = sAl[kb+tig+4][m+8];
            }
            #pragma unroll
            for (int nj = 0; nj < 4; nj++) {
                int n = wn0 + nj*8 + gid;
                bh[nj][0] = sBh[kb+tig  ][n];
                bh[nj][1] = sBh[kb+tig+4][n];
                bl[nj][0] = sBl[kb+tig  ][n];
                bl[nj][1] = sBl[kb+tig+4][n];
            }
            #pragma unroll
            for (int mi = 0; mi < 4; mi++)
                #pragma unroll
                for (int nj = 0; nj < 4; nj++) {
                    mma_bf16(acc[mi][nj], ah[mi], bh[nj]);
                    mma_bf16(acc[mi][nj], ah[mi], bl[nj]);
                    mma_bf16(acc[mi][nj], al[mi], bh[nj]);
                }
        }
        __syncthreads();
    }

    #pragma unroll
    for (int mi = 0; mi < 4; mi++) {
        #pragma unroll
        for (int half = 0; half < 2; half++) {
            int rowL = wm0 + mi*16 + gid + half*8;
            float* optr = O_s + (size_t)rowL*oRow;
            #pragma unroll
            for (int nj = 0; nj < 4; nj++) {
                int col = wn0 + nj*8 + 2*tig;
                float2 f2;
                f2.x = acc[mi][nj][half*2+0];
                f2.y = acc[mi][nj][half*2+1];
                *(float2*)(optr + col) = f2;
            }
        }
    }
}
__global__ void __launch_bounds__(256) agg_H_mma_kernel(){
    agg_mma_body(g_vHkm_h, g_vHkm_l, g_aHkm_h, g_aHkm_l, g_oH,
                 (long)WW*CC*HH, (long)CC*HH, (long)HH);
}
__global__ void __launch_bounds__(256) agg_W_mma_kernel(float* __restrict__ out){
    agg_mma_body(g_vWkm_h, g_vWkm_l, g_aWkm_h, g_aWkm_l, out,
                 (long)CC*HWW, (long)WW, (long)HWW);
}

// ---------------- combine: out = GAMMA*(out_H^T + out_W) + x ----------------
__global__ void combine_kernel(const float* __restrict__ x, float* __restrict__ out)
{
    __shared__ float t[32][33];
    int bc = blockIdx.z;
    int b = bc >> 9, c = bc & 511;
    int w0 = blockIdx.x*32, h0 = blockIdx.y*32;
    int tx = threadIdx.x, ty = threadIdx.y;
    #pragma unroll
    for (int k = 0; k < 32; k += 8) {
        int w = w0 + ty + k;
        int h = h0 + tx;
        t[ty+k][tx] = g_oH[(((size_t)b*WW + w)*CC + c)*HH + h];
    }
    __syncthreads();
    #pragma unroll
    for (int k = 0; k < 32; k += 8) {
        int h = h0 + ty + k;
        int w = w0 + tx;
        size_t idx = ((size_t)bc*HH + h)*WW + w;
        out[idx] = GAMMA_*(t[tx][ty+k] + out[idx]) + x[idx];
    }
}

// ---------------- launch ----------------
extern "C" void kernel_launch(void* const* d_in, const int* in_sizes, int n_in,
                              void* d_out, int out_size)
{
    const float* x  = (const float*)d_in[0];
    const float* Wq = (const float*)d_in[1];
    const float* bq = (const float*)d_in[2];
    const float* Wk = (const float*)d_in[3];
    const float* bk = (const float*)d_in[4];
    const float* Wv = (const float*)d_in[5];
    const float* bv = (const float*)d_in[6];
    float* out = (float*)d_out;

    dim3 tb(32, 8);

    pack_W_kernel<<<160, 256>>>(Wq, Wk, Wv);
    pack_x_kernel<<<(BB*256*HWW/4)/256, 256>>>(x);

    mma_proj_kernel<<<dim3(5, HWW/128, BB), 256>>>(bq, bk, bv);

    // q/k energy-operand packs
    packA_q_kernel<<<dim3(4, 2, BB*HH), tb>>>();
    packA_k_kernel<<<dim3(4, 2, BB*HH), tb>>>();
    packB_q_kernel<<<dim3(4, 4, BB*8), 256>>>();
    packB_k_kernel<<<dim3(4, 4, BB*8), 256>>>();

    // v packs
    v_pack_W_kernel<<<dim3(16, 4, BB*HH), tb>>>();
    v_packH_kernel<<<dim3(4, 16, BB*16), 256>>>();

    // energies (HMMA)
    energy_H_mma_kernel<<<dim3(1, 1, BB*WW), 256>>>();
    energy_W_mma_kernel<<<dim3(1, 1, BB*HH), 256>>>();

    // softmax statistics + packed attention
    reduce_kernel<<<(BB*HH*WW)/8, 256>>>();
    finalize_H_kernel<<<dim3(4, 4, BB*WW), tb>>>();
    finalize_W_kernel<<<dim3(4, 4, BB*HH), tb>>>();

    // aggregation (HMMA)
    agg_H_mma_kernel<<<dim3(4, 1, BB*WW), 256>>>();
    agg_W_mma_kernel<<<dim3(4, 1, BB*HH), 256>>>(out);

    combine_kernel<<<dim3(WW/32, HH/32, BB*CC), tb>>>(x, out);
}

// round 9
// speedup vs baseline: 2.8077x; 1.0986x over previous
#include <cuda_runtime.h>
#include <cuda_bf16.h>
#include <cstdint>

#define BB 8
#define CC 512
#define DQ 64
#define HH 128
#define WW 128
#define HWW 16384
#define GAMMA_ 1.0f

// ---------------- scratch (device globals; no allocation) ----------------
__device__ float g_q [BB*DQ*HWW];        // [B,DQ,H,W]
__device__ float g_k [BB*DQ*HWW];        // [B,DQ,H,W]
__device__ float g_eH[BB*WW*HH*HH];      // [B,W,H,G]  raw energies (masked)
__device__ float g_eW[BB*HH*WW*WW];      // [B,H,W,V]  raw energies
__device__ float g_oH[BB*WW*CC*HH];      // [B,W,C,H]
__device__ float2 g_statH[BB*WW*HH];     // per (b,w,h): partial (max, sum) over H rows
__device__ float2 g_statW[BB*HH*WW];     // per (b,h,w): partial over W rows
__device__ float2 g_stat [BB*HWW];       // combined (max, 1/sum)

// packed bf16 hi/lo (uint32 = two consecutive-K bf16, low half = even k)
__device__ uint32_t g_Wp_h[256*640];               // [kp][m]
__device__ uint32_t g_Wp_l[256*640];
// K-major operands for aggregation ([slice][kp=64][cols])
__device__ uint32_t g_vWkm_h[(size_t)BB*HH*64*512]; // [b*HH+h][wp][c]
__device__ uint32_t g_vWkm_l[(size_t)BB*HH*64*512];
__device__ uint32_t g_vHkm_h[(size_t)BB*WW*64*512]; // [b*WW+w][hp][c]
__device__ uint32_t g_vHkm_l[(size_t)BB*WW*64*512];
__device__ uint32_t g_aHkm_h[(size_t)BB*WW*64*128]; // [b*WW+w][gp][h]
__device__ uint32_t g_aHkm_l[(size_t)BB*WW*64*128];
__device__ uint32_t g_aWkm_h[(size_t)BB*HH*64*128]; // [b*HH+h][vp][w]
__device__ uint32_t g_aWkm_l[(size_t)BB*HH*64*128];
// K-major operands for energy ([slice][kp=32][128])
__device__ uint32_t g_qWkm_h[(size_t)BB*HH*32*128]; // [b*HH+h][dp][w]
__device__ uint32_t g_qWkm_l[(size_t)BB*HH*32*128];
__device__ uint32_t g_kWkm_h[(size_t)BB*HH*32*128];
__device__ uint32_t g_kWkm_l[(size_t)BB*HH*32*128];
__device__ uint32_t g_qHkm_h[(size_t)BB*WW*32*128]; // [b*WW+w][dp][h]
__device__ uint32_t g_qHkm_l[(size_t)BB*WW*32*128];
__device__ uint32_t g_kHkm_h[(size_t)BB*WW*32*128];
__device__ uint32_t g_kHkm_l[(size_t)BB*WW*32*128];

// ---------------- helpers ----------------
__device__ __forceinline__ void split_pack(float v0, float v1, uint32_t& hi, uint32_t& lo){
    __nv_bfloat16 h0 = __float2bfloat16(v0);
    __nv_bfloat16 h1 = __float2bfloat16(v1);
    __nv_bfloat16 l0 = __float2bfloat16(v0 - __bfloat162float(h0));
    __nv_bfloat16 l1 = __float2bfloat16(v1 - __bfloat162float(h1));
    hi = ((uint32_t)__bfloat16_as_ushort(h1) << 16) | (uint32_t)__bfloat16_as_ushort(h0);
    lo = ((uint32_t)__bfloat16_as_ushort(l1) << 16) | (uint32_t)__bfloat16_as_ushort(l0);
}
__device__ __forceinline__ float b2f_lo(uint32_t u){
    return __bfloat162float(__ushort_as_bfloat16((unsigned short)(u & 0xffffu)));
}
__device__ __forceinline__ float b2f_hi(uint32_t u){
    return __bfloat162float(__ushort_as_bfloat16((unsigned short)(u >> 16)));
}
__device__ __forceinline__ void mma_bf16(float* c, const uint32_t* a, const uint32_t* b){
    asm volatile("mma.sync.aligned.m16n8k16.row.col.f32.bf16.bf16.f32 "
        "{%0,%1,%2,%3}, {%4,%5,%6,%7}, {%8,%9}, {%0,%1,%2,%3};"
        : "+f"(c[0]), "+f"(c[1]), "+f"(c[2]), "+f"(c[3])
        : "r"(a[0]), "r"(a[1]), "r"(a[2]), "r"(a[3]), "r"(b[0]), "r"(b[1]));
}

// ---------------- pack W (tiny) ----------------
__global__ void __launch_bounds__(256) pack_W_kernel(const float* __restrict__ Wq,
                                                     const float* __restrict__ Wk,
                                                     const float* __restrict__ Wv)
{
    int u = blockIdx.x * 256 + threadIdx.x;
    if (u >= 256*160) return;
    int kp = u / 160;
    int m4 = u - kp*160;
    int m = m4*4;
    int c0 = 2*kp, c1 = 2*kp+1;
    float v0[4], v1[4];
    #pragma unroll
    for (int j = 0; j < 4; j++) {
        int mm = m + j;
        if (mm < 64)       { v0[j] = Wq[(size_t)c0*DQ + mm];       v1[j] = Wq[(size_t)c1*DQ + mm]; }
        else if (mm < 128) { v0[j] = Wk[(size_t)c0*DQ + mm-64];    v1[j] = Wk[(size_t)c1*DQ + mm-64]; }
        else               { v0[j] = Wv[(size_t)c0*CC + mm-128];   v1[j] = Wv[(size_t)c1*CC + mm-128]; }
    }
    uint4 hi, lo;
    split_pack(v0[0], v1[0], hi.x, lo.x);
    split_pack(v0[1], v1[1], hi.y, lo.y);
    split_pack(v0[2], v1[2], hi.z, lo.z);
    split_pack(v0[3], v1[3], hi.w, lo.w);
    *(uint4*)(g_Wp_h + (size_t)kp*640 + m) = hi;
    *(uint4*)(g_Wp_l + (size_t)kp*640 + m) = lo;
}

// ---------------- HMMA projection GEMM ----------------
// B operand: x fp32 read directly, split-packed into smem in the loader.
// v output rows (mTile>0) written directly as packed vWkm (w-pairs).
__global__ void __launch_bounds__(256) mma_proj_kernel(
    const float* __restrict__ x,
    const float* __restrict__ bq, const float* __restrict__ bk, const float* __restrict__ bvv)
{
    __shared__ uint32_t sAh[16][136], sAl[16][136], sBh[16][136], sBl[16][136];

    const int tid = threadIdx.x;
    const int wid = tid >> 5, lane = tid & 31;
    const int gid = lane >> 2, tig = lane & 3;
    const int wm0 = (wid >> 2) * 64;
    const int wn0 = (wid & 3) * 32;
    const int mTile = blockIdx.x * 128;
    const int nTile = blockIdx.y * 128;
    const int b = blockIdx.z;

    float acc[4][4][4];
    #pragma unroll
    for (int i = 0; i < 4; i++)
        #pragma unroll
        for (int j = 0; j < 4; j++)
            #pragma unroll
            for (int r = 0; r < 4; r++) acc[i][j][r] = 0.f;

    const float* xB = x + (size_t)b*CC*HWW + nTile;

    for (int it = 0; it < 16; ++it) {
        const int kp0 = it * 16;
        #pragma unroll
        for (int i = 0; i < 2; i++) {
            int f = tid + i*256;
            int kp = f >> 5, c4 = (f & 31) * 4;
            *(uint4*)&sAh[kp][c4] = *(const uint4*)&g_Wp_h[(size_t)(kp0+kp)*640 + mTile + c4];
            *(uint4*)&sAl[kp][c4] = *(const uint4*)&g_Wp_l[(size_t)(kp0+kp)*640 + mTile + c4];
            const float* p0 = xB + (size_t)(2*(kp0+kp))*HWW + c4;
            float4 r0 = *(const float4*)p0;
            float4 r1 = *(const float4*)(p0 + HWW);
            uint4 bh4, bl4;
            split_pack(r0.x, r1.x, bh4.x, bl4.x);
            split_pack(r0.y, r1.y, bh4.y, bl4.y);
            split_pack(r0.z, r1.z, bh4.z, bl4.z);
            split_pack(r0.w, r1.w, bh4.w, bl4.w);
            *(uint4*)&sBh[kp][c4] = bh4;
            *(uint4*)&sBl[kp][c4] = bl4;
        }
        __syncthreads();
        #pragma unroll
        for (int ks = 0; ks < 2; ks++) {
            const int kb = ks * 8;
            uint32_t ah[4][4], al[4][4], bh[4][2], bl[4][2];
            #pragma unroll
            for (int mi = 0; mi < 4; mi++) {
                int m = wm0 + mi*16 + gid;
                ah[mi][0] = sAh[kb+tig  ][m];
                ah[mi][1] = sAh[kb+tig  ][m+8];
                ah[mi][2] = sAh[kb+tig+4][m];
                ah[mi][3] = sAh[kb+tig+4][m+8];
                al[mi][0] = sAl[kb+tig  ][m];
                al[mi][1] = sAl[kb+tig  ][m+8];
                al[mi][2] = sAl[kb+tig+4][m];
                al[mi][3] = sAl[kb+tig+4][m+8];
            }
            #pragma unroll
            for (int nj = 0; nj < 4; nj++) {
                int n = wn0 + nj*8 + gid;
                bh[nj][0] = sBh[kb+tig  ][n];
                bh[nj][1] = sBh[kb+tig+4][n];
                bl[nj][0] = sBl[kb+tig  ][n];
                bl[nj][1] = sBl[kb+tig+4][n];
            }
            #pragma unroll
            for (int mi = 0; mi < 4; mi++)
                #pragma unroll
                for (int nj = 0; nj < 4; nj++) {
                    mma_bf16(acc[mi][nj], ah[mi], bh[nj]);
                    mma_bf16(acc[mi][nj], ah[mi], bl[nj]);
                    mma_bf16(acc[mi][nj], al[mi], bh[nj]);
                }
        }
        __syncthreads();
    }

    if (mTile == 0) {
        // q/k rows -> fp32 (needed for energy packs)
        #pragma unroll
        for (int mi = 0; mi < 4; mi++) {
            #pragma unroll
            for (int half = 0; half < 2; half++) {
                int row = wm0 + mi*16 + gid + half*8;
                float bias; float* optr;
                if (row < 64) { bias = bq[row];    optr = g_q + ((size_t)b*DQ + row)     *HWW; }
                else          { bias = bk[row-64]; optr = g_k + ((size_t)b*DQ + (row-64))*HWW; }
                #pragma unroll
                for (int nj = 0; nj < 4; nj++) {
                    int col = nTile + wn0 + nj*8 + 2*tig;
                    float2 f2;
                    f2.x = acc[mi][nj][half*2+0] + bias;
                    f2.y = acc[mi][nj][half*2+1] + bias;
                    *(float2*)(optr + col) = f2;
                }
            }
        }
    } else {
        // v rows -> packed vWkm directly. nTile covers one (b, h) row; cols are w.
        const int hIdx = blockIdx.y;
        #pragma unroll
        for (int mi = 0; mi < 4; mi++) {
            #pragma unroll
            for (int half = 0; half < 2; half++) {
                int c = mTile - 128 + wm0 + mi*16 + gid + half*8;
                float bias = bvv[c];
                #pragma unroll
                for (int nj = 0; nj < 4; nj++) {
                    int col = wn0 + nj*8 + 2*tig;        // w (even), pair (col, col+1)
                    uint32_t hh, ll;
                    split_pack(acc[mi][nj][half*2+0] + bias,
                               acc[mi][nj][half*2+1] + bias, hh, ll);
                    size_t o = ((size_t)(b*HH + hIdx)*64 + (col>>1))*512 + c;
                    g_vWkm_h[o] = hh; g_vWkm_l[o] = ll;
                }
            }
        }
    }
}

// ---------------- v pack H-orientation from packed vWkm (no smem, coalesced) ----
__global__ void __launch_bounds__(256) v_packH_kernel()
{
    int u = blockIdx.x*256 + threadIdx.x;     // ((b*64+wp)*64+hp)*128 + c4
    int c4 = u & 127;
    int hp = (u >> 7) & 63;
    int wp = (u >> 13) & 63;
    int b  = u >> 19;
    size_t i0 = ((size_t)(b*HH + 2*hp  )*64 + wp)*512 + c4*4;
    size_t i1 = ((size_t)(b*HH + 2*hp+1)*64 + wp)*512 + c4*4;
    uint4 h0 = *(const uint4*)(g_vWkm_h + i0), l0 = *(const uint4*)(g_vWkm_l + i0);
    uint4 h1 = *(const uint4*)(g_vWkm_h + i1), l1 = *(const uint4*)(g_vWkm_l + i1);
    uint4 oh0, ol0, oh1, ol1;
    // w even (low16), w odd (high16); pair along h: (2hp, 2hp+1)
    split_pack(b2f_lo(h0.x)+b2f_lo(l0.x), b2f_lo(h1.x)+b2f_lo(l1.x), oh0.x, ol0.x);
    split_pack(b2f_lo(h0.y)+b2f_lo(l0.y), b2f_lo(h1.y)+b2f_lo(l1.y), oh0.y, ol0.y);
    split_pack(b2f_lo(h0.z)+b2f_lo(l0.z), b2f_lo(h1.z)+b2f_lo(l1.z), oh0.z, ol0.z);
    split_pack(b2f_lo(h0.w)+b2f_lo(l0.w), b2f_lo(h1.w)+b2f_lo(l1.w), oh0.w, ol0.w);
    split_pack(b2f_hi(h0.x)+b2f_hi(l0.x), b2f_hi(h1.x)+b2f_hi(l1.x), oh1.x, ol1.x);
    split_pack(b2f_hi(h0.y)+b2f_hi(l0.y), b2f_hi(h1.y)+b2f_hi(l1.y), oh1.y, ol1.y);
    split_pack(b2f_hi(h0.z)+b2f_hi(l0.z), b2f_hi(h1.z)+b2f_hi(l1.z), oh1.z, ol1.z);
    split_pack(b2f_hi(h0.w)+b2f_hi(l0.w), b2f_hi(h1.w)+b2f_hi(l1.w), oh1.w, ol1.w);
    size_t o0 = ((size_t)(b*WW + 2*wp  )*64 + hp)*512 + c4*4;
    size_t o1 = ((size_t)(b*WW + 2*wp+1)*64 + hp)*512 + c4*4;
    *(uint4*)(g_vHkm_h + o0) = oh0; *(uint4*)(g_vHkm_l + o0) = ol0;
    *(uint4*)(g_vHkm_h + o1) = oh1; *(uint4*)(g_vHkm_l + o1) = ol1;
}

// ---------------- packA/packB: q/k energy operands (validated R7) ----------------
__device__ __forceinline__ void packA_body(const float* __restrict__ src,
                                           uint32_t* __restrict__ dh,
                                           uint32_t* __restrict__ dl)
{
    __shared__ float t[32][33];
    int s = blockIdx.z;                 // b*HH + h
    int b = s >> 7, h = s & 127;
    int w0 = blockIdx.x*32, d0 = blockIdx.y*32;
    int tx = threadIdx.x, ty = threadIdx.y;
    const float* S = src + (size_t)b*DQ*HWW + (size_t)h*WW;
    #pragma unroll
    for (int j = 0; j < 32; j += 8)
        t[ty+j][tx] = S[(size_t)(d0+ty+j)*HWW + w0 + tx];
    __syncthreads();
    #pragma unroll
    for (int j = 0; j < 16; j += 8) {
        int kp = ty + j;
        uint32_t hi, lo;
        split_pack(t[2*kp][tx], t[2*kp+1][tx], hi, lo);
        size_t o = ((size_t)s*32 + (d0>>1) + kp)*128 + w0 + tx;
        dh[o] = hi; dl[o] = lo;
    }
}
__global__ void packA_q_kernel(){ packA_body(g_q, g_qWkm_h, g_qWkm_l); }
__global__ void packA_k_kernel(){ packA_body(g_k, g_kWkm_h, g_kWkm_l); }

__device__ __forceinline__ void packB_body(const float* __restrict__ src,
                                           uint32_t* __restrict__ dh,
                                           uint32_t* __restrict__ dl)
{
    __shared__ float t[8][32][33];
    int z = blockIdx.z;                 // b*8 + d8
    int b = z >> 3, d0 = (z & 7) * 8;
    int w0 = blockIdx.x*32, h0 = blockIdx.y*32;
    int tid = threadIdx.x;
    int tx = tid & 31, ty = tid >> 5;
    #pragma unroll
    for (int dd = 0; dd < 8; dd++)
        #pragma unroll
        for (int j = 0; j < 32; j += 8)
            t[dd][ty+j][tx] = src[((size_t)b*DQ + d0+dd)*HWW + (size_t)(h0+ty+j)*WW + w0 + tx];
    __syncthreads();
    #pragma unroll
    for (int it = 0; it < 16; it++) {
        int idx = tid + it*256;
        int hl = idx & 31, wl = (idx >> 5) & 31, dpl = idx >> 10;
        uint32_t hi, lo;
        split_pack(t[2*dpl][hl][wl], t[2*dpl+1][hl][wl], hi, lo);
        size_t o = (((size_t)b*WW + w0 + wl)*32 + (d0>>1) + dpl)*128 + h0 + hl;
        dh[o] = hi; dl[o] = lo;
    }
}
__global__ void __launch_bounds__(256) packB_q_kernel(){ packB_body(g_q, g_qHkm_h, g_qHkm_l); }
__global__ void __launch_bounds__(256) packB_k_kernel(){ packB_body(g_k, g_kHkm_h, g_kHkm_l); }

// ---------------- HMMA energy GEMM + per-row stat partials ----------------
template<int MASK>
__device__ __forceinline__ void energy_mma_body(
    const uint32_t* __restrict__ Qh, const uint32_t* __restrict__ Ql,
    const uint32_t* __restrict__ Kh, const uint32_t* __restrict__ Kl,
    float* __restrict__ E, float2* __restrict__ statOut)
{
    __shared__ uint32_t sAh[16][136], sAl[16][136], sBh[16][136], sBl[16][136];
    __shared__ float red[128][17];
    __shared__ float rmax[128];

    const int tid = threadIdx.x;
    const int wid = tid >> 5, lane = tid & 31;
    const int gid = lane >> 2, tig = lane & 3;
    const int wm0 = (wid >> 2) * 64;
    const int wn0 = (wid & 3) * 32;
    const int cg  = (wid & 3) * 4 + tig;
    const int s = blockIdx.z;

    const uint32_t* Qh_s = Qh + (size_t)s*32*128;
    const uint32_t* Ql_s = Ql + (size_t)s*32*128;
    const uint32_t* Kh_s = Kh + (size_t)s*32*128;
    const uint32_t* Kl_s = Kl + (size_t)s*32*128;
    float* E_s = E + (size_t)s*16384;

    float acc[4][4][4];
    #pragma unroll
    for (int i = 0; i < 4; i++)
        #pragma unroll
        for (int j = 0; j < 4; j++)
            #pragma unroll
            for (int r = 0; r < 4; r++) acc[i][j][r] = 0.f;

    for (int ch = 0; ch < 2; ++ch) {
        const int kp0 = ch * 16;
        #pragma unroll
        for (int i = 0; i < 2; i++) {
            int f = tid + i*256;
            int kp = f >> 5, c4 = (f & 31) * 4;
            *(uint4*)&sAh[kp][c4] = *(const uint4*)(Qh_s + (size_t)(kp0+kp)*128 + c4);
            *(uint4*)&sAl[kp][c4] = *(const uint4*)(Ql_s + (size_t)(kp0+kp)*128 + c4);
            *(uint4*)&sBh[kp][c4] = *(const uint4*)(Kh_s + (size_t)(kp0+kp)*128 + c4);
            *(uint4*)&sBl[kp][c4] = *(const uint4*)(Kl_s + (size_t)(kp0+kp)*128 + c4);
        }
        __syncthreads();
        #pragma unroll
        for (int ks = 0; ks < 2; ks++) {
            const int kb = ks * 8;
            uint32_t ah[4][4], al[4][4], bh[4][2], bl[4][2];
            #pragma unroll
            for (int mi = 0; mi < 4; mi++) {
                int m = wm0 + mi*16 + gid;
                ah[mi][0] = sAh[kb+tig  ][m];
                ah[mi][1] = sAh[kb+tig  ][m+8];
                ah[mi][2] = sAh[kb+tig+4][m];
                ah[mi][3] = sAh[kb+tig+4][m+8];
                al[mi][0] = sAl[kb+tig  ][m];
                al[mi][1] = sAl[kb+tig  ][m+8];
                al[mi][2] = sAl[kb+tig+4][m];
                al[mi][3] = sAl[kb+tig+4][m+8];
            }
            #pragma unroll
            for (int nj = 0; nj < 4; nj++) {
                int n = wn0 + nj*8 + gid;
                bh[nj][0] = sBh[kb+tig  ][n];
                bh[nj][1] = sBh[kb+tig+4][n];
                bl[nj][0] = sBl[kb+tig  ][n];
                bl[nj][1] = sBl[kb+tig+4][n];
            }
            #pragma unroll
            for (int mi = 0; mi < 4; mi++)
                #pragma unroll
                for (int nj = 0; nj < 4; nj++) {
                    mma_bf16(acc[mi][nj], ah[mi], bh[nj]);
                    mma_bf16(acc[mi][nj], ah[mi], bl[nj]);
                    mma_bf16(acc[mi][nj], al[mi], bh[nj]);
                }
        }
        __syncthreads();
    }

    const float NINF = __int_as_float(0xff800000);
    // apply mask in-place
    if (MASK) {
        #pragma unroll
        for (int mi = 0; mi < 4; mi++)
            #pragma unroll
            for (int half = 0; half < 2; half++) {
                int row = wm0 + mi*16 + gid + half*8;
                #pragma unroll
                for (int nj = 0; nj < 4; nj++) {
                    int col = wn0 + nj*8 + 2*tig;
                    if (row == col)   acc[mi][nj][half*2+0] = NINF;
                    if (row == col+1) acc[mi][nj][half*2+1] = NINF;
                }
            }
    }

    // write energies
    #pragma unroll
    for (int mi = 0; mi < 4; mi++)
        #pragma unroll
        for (int half = 0; half < 2; half++) {
            int row = wm0 + mi*16 + gid + half*8;
            #pragma unroll
            for (int nj = 0; nj < 4; nj++) {
                int col = wn0 + nj*8 + 2*tig;
                float2 f2;
                f2.x = acc[mi][nj][half*2+0];
                f2.y = acc[mi][nj][half*2+1];
                *(float2*)(E_s + (size_t)row*128 + col) = f2;
            }
        }

    // per-row stats: phase 1 = local max
    #pragma unroll
    for (int mi = 0; mi < 4; mi++)
        #pragma unroll
        for (int half = 0; half < 2; half++) {
            int row = wm0 + mi*16 + gid + half*8;
            float m8 = NINF;
            #pragma unroll
            for (int nj = 0; nj < 4; nj++) {
                m8 = fmaxf(m8, acc[mi][nj][half*2+0]);
                m8 = fmaxf(m8, acc[mi][nj][half*2+1]);
            }
            red[row][cg] = m8;
        }
    __syncthreads();
    if (tid < 128) {
        float m = red[tid][0];
        #pragma unroll
        for (int j = 1; j < 16; j++) m = fmaxf(m, red[tid][j]);
        rmax[tid] = m;
    }
    __syncthreads();
    // phase 2: local exp-sum
    #pragma unroll
    for (int mi = 0; mi < 4; mi++)
        #pragma unroll
        for (int half = 0; half < 2; half++) {
            int row = wm0 + mi*16 + gid + half*8;
            float rm = rmax[row];
            float s8 = 0.f;
            #pragma unroll
            for (int nj = 0; nj < 4; nj++) {
                s8 += __expf(acc[mi][nj][half*2+0] - rm);
                s8 += __expf(acc[mi][nj][half*2+1] - rm);
            }
            red[row][cg] = s8;
        }
    __syncthreads();
    if (tid < 128) {
        float ssum = red[tid][0];
        #pragma unroll
        for (int j = 1; j < 16; j++) ssum += red[tid][j];
        statOut[(size_t)s*128 + tid] = make_float2(rmax[tid], ssum);
    }
}
__global__ void __launch_bounds__(256) energy_H_mma_kernel(){
    energy_mma_body<1>(g_qHkm_h, g_qHkm_l, g_kHkm_h, g_kHkm_l, g_eH, g_statH);
}
__global__ void __launch_bounds__(256) energy_W_mma_kernel(){
    energy_mma_body<0>(g_qWkm_h, g_qWkm_l, g_kWkm_h, g_kWkm_l, g_eW, g_statW);
}

// ---------------- merge orientation stats ----------------
__global__ void __launch_bounds__(256) combine_stat_kernel()
{
    int u = blockIdx.x*256 + threadIdx.x;   // b*HWW + h*WW + w
    int b = u >> 14;
    int hw = u & 16383;
    int h = hw >> 7, w = hw & 127;
    float2 sh = g_statH[(size_t)(b*WW + w)*128 + h];
    float2 sw = g_statW[(size_t)(b*HH + h)*128 + w];
    float m = fmaxf(sh.x, sw.x);
    float s = sh.y*__expf(sh.x - m) + sw.y*__expf(sw.x - m);
    g_stat[u] = make_float2(m, 1.0f/s);
}

// ---------------- finalize: raw e -> exp-normalized packed K-major att ----------------
__device__ __forceinline__ void finalize_body(const float* __restrict__ src,
                                              uint32_t* __restrict__ dh,
                                              uint32_t* __restrict__ dl,
                                              size_t statBase, int statStride)
{
    __shared__ float t[32][33];
    int s = blockIdx.z;
    int r0 = blockIdx.x*32, k0 = blockIdx.y*32;
    const float* S = src + (size_t)s*16384;
    int tx = threadIdx.x, ty = threadIdx.y;
    #pragma unroll
    for (int j = 0; j < 32; j += 8)
        t[ty+j][tx] = S[(size_t)(r0+ty+j)*128 + k0 + tx];
    __syncthreads();
    float2 st = g_stat[statBase + (size_t)(r0+tx)*statStride];
    #pragma unroll
    for (int j = 0; j < 16; j += 8) {
        int kp = ty + j;
        float a0 = __expf(t[tx][2*kp  ] - st.x) * st.y;
        float a1 = __expf(t[tx][2*kp+1] - st.x) * st.y;
        uint32_t hi, lo;
        split_pack(a0, a1, hi, lo);
        size_t o = ((size_t)s*64 + (k0>>1) + kp)*128 + r0 + tx;
        dh[o] = hi; dl[o] = lo;
    }
}
__global__ void finalize_H_kernel(){
    int s = blockIdx.z;                // (b, w); rows = h
    int b = s >> 7, w = s & 127;
    finalize_body(g_eH, g_aHkm_h, g_aHkm_l, (size_t)b*HWW + w, WW);
}
__global__ void finalize_W_kernel(){
    int s = blockIdx.z;                // (b, h); rows = w
    int b = s >> 7, h = s & 127;
    finalize_body(g_eW, g_aWkm_h, g_aWkm_l, (size_t)b*HWW + (size_t)h*WW, 1);
}

// ---------------- HMMA aggregation (validated R6; optional fused +x) ----------------
__device__ __forceinline__ void agg_mma_body(
    const uint32_t* __restrict__ Vh, const uint32_t* __restrict__ Vl,
    const uint32_t* __restrict__ Ah, const uint32_t* __restrict__ Al,
    float* __restrict__ O, long oB, long oS, long oRow,
    const float* __restrict__ xAdd)
{
    __shared__ uint32_t sAh[16][136], sAl[16][136], sBh[16][136], sBl[16][136];

    const int tid = threadIdx.x;
    const int wid = tid >> 5, lane = tid & 31;
    const int gid = lane >> 2, tig = lane & 3;
    const int wm0 = (wid >> 2) * 64;
    const int wn0 = (wid & 3) * 32;
    const int mTile = blockIdx.x * 128;
    const int s = blockIdx.z;
    const int b = s >> 7, ss = s & 127;

    const uint32_t* Vh_s = Vh + (size_t)s*64*512 + mTile;
    const uint32_t* Vl_s = Vl + (size_t)s*64*512 + mTile;
    const uint32_t* Ah_s = Ah + (size_t)s*64*128;
    const uint32_t* Al_s = Al + (size_t)s*64*128;
    const size_t oBase = (size_t)b*oB + (size_t)ss*oS + (size_t)mTile*oRow;
    float* O_s = O + oBase;
    const float* X_s = xAdd ? (xAdd + oBase) : nullptr;

    float acc[4][4][4];
    #pragma unroll
    for (int i = 0; i < 4; i++)
        #pragma unroll
        for (int j = 0; j < 4; j++)
            #pragma unroll
            for (int r = 0; r < 4; r++) acc[i][j][r] = 0.f;

    for (int ch = 0; ch < 4; ++ch) {
        const int kp0 = ch * 16;
        #pragma unroll
        for (int i = 0; i < 2; i++) {
            int f = tid + i*256;
            int kp = f >> 5, c4 = (f & 31) * 4;
            *(uint4*)&sAh[kp][c4] = *(const uint4*)(Vh_s + (size_t)(kp0+kp)*512 + c4);
            *(uint4*)&sAl[kp][c4] = *(const uint4*)(Vl_s + (size_t)(kp0+kp)*512 + c4);
            *(uint4*)&sBh[kp][c4] = *(const uint4*)(Ah_s + (size_t)(kp0+kp)*128 + c4);
            *(uint4*)&sBl[kp][c4] = *(const uint4*)(Al_s + (size_t)(kp0+kp)*128 + c4);
        }
        __syncthreads();
        #pragma unroll
        for (int ks = 0; ks < 2; ks++) {
            const int kb = ks * 8;
            uint32_t ah[4][4], al[4][4], bh[4][2], bl[4][2];
            #pragma unroll
            for (int mi = 0; mi < 4; mi++) {
                int m = wm0 + mi*16 + gid;
                ah[mi][0] = sAh[kb+tig  ][m];
                ah[mi][1] = sAh[kb+tig  ][m+8];
                ah[mi][2] = sAh[kb+tig+4][m];
                ah[mi][3] = sAh[kb+tig+4][m+8];
                al[mi][0] = sAl[kb+tig  ][m];
                al[mi][1] = sAl[kb+tig  ][m+8];
                al[mi][2] = sAl[kb+tig+4][m];
                al[mi][3] = sAl[kb+tig+4][m+8];
            }
            #pragma unroll
            for (int nj = 0; nj < 4; nj++) {
                int n = wn0 + nj*8 + gid;
                bh[nj][0] = sBh[kb+tig  ][n];
                bh[nj][1] = sBh[kb+tig+4][n];
                bl[nj][0] = sBl[kb+tig  ][n];
                bl[nj][1] = sBl[kb+tig+4][n];
            }
            #pragma unroll
            for (int mi = 0; mi < 4; mi++)
                #pragma unroll
                for (int nj = 0; nj < 4; nj++) {
                    mma_bf16(acc[mi][nj], ah[mi], bh[nj]);
                    mma_bf16(acc[mi][nj], ah[mi], bl[nj]);
                    mma_bf16(acc[mi][nj], al[mi], bh[nj]);
                }
        }
        __syncthreads();
    }

    #pragma unroll
    for (int mi = 0; mi < 4; mi++) {
        #pragma unroll
        for (int half = 0; half < 2; half++) {
            int rowL = wm0 + mi*16 + gid + half*8;
            size_t roff = (size_t)rowL*oRow;
            #pragma unroll
            for (int nj = 0; nj < 4; nj++) {
                int col = wn0 + nj*8 + 2*tig;
                float2 f2;
                f2.x = acc[mi][nj][half*2+0];
                f2.y = acc[mi][nj][half*2+1];
                if (X_s) {
                    float2 xv = *(const float2*)(X_s + roff + col);
                    f2.x += xv.x; f2.y += xv.y;
                }
                *(float2*)(O_s + roff + col) = f2;
            }
        }
    }
}
__global__ void __launch_bounds__(256) agg_H_mma_kernel(){
    agg_mma_body(g_vHkm_h, g_vHkm_l, g_aHkm_h, g_aHkm_l, g_oH,
                 (long)WW*CC*HH, (long)CC*HH, (long)HH, nullptr);
}
__global__ void __launch_bounds__(256) agg_W_mma_kernel(float* __restrict__ out,
                                                        const float* __restrict__ x){
    agg_mma_body(g_vWkm_h, g_vWkm_l, g_aWkm_h, g_aWkm_l, out,
                 (long)CC*HWW, (long)WW, (long)HWW, x);
}

// ---------------- combine: out += GAMMA*out_H^T  (out already = out_W + x) ----------
__global__ void combine_kernel(float* __restrict__ out)
{
    __shared__ float t[32][33];
    int bc = blockIdx.z;
    int b = bc >> 9, c = bc & 511;
    int w0 = blockIdx.x*32, h0 = blockIdx.y*32;
    int tx = threadIdx.x, ty = threadIdx.y;
    #pragma unroll
    for (int k = 0; k < 32; k += 8) {
        int w = w0 + ty + k;
        int h = h0 + tx;
        t[ty+k][tx] = g_oH[(((size_t)b*WW + w)*CC + c)*HH + h];
    }
    __syncthreads();
    #pragma unroll
    for (int k = 0; k < 32; k += 8) {
        int h = h0 + ty + k;
        int w = w0 + tx;
        size_t idx = ((size_t)bc*HH + h)*WW + w;
        out[idx] = GAMMA_*t[tx][ty+k] + out[idx];
    }
}

// ---------------- launch ----------------
extern "C" void kernel_launch(void* const* d_in, const int* in_sizes, int n_in,
                              void* d_out, int out_size)
{
    const float* x  = (const float*)d_in[0];
    const float* Wq = (const float*)d_in[1];
    const float* bq = (const float*)d_in[2];
    const float* Wk = (const float*)d_in[3];
    const float* bk = (const float*)d_in[4];
    const float* Wv = (const float*)d_in[5];
    const float* bv = (const float*)d_in[6];
    float* out = (float*)d_out;

    dim3 tb(32, 8);

    pack_W_kernel<<<160, 256>>>(Wq, Wk, Wv);

    mma_proj_kernel<<<dim3(5, HWW/128, BB), 256>>>(x, bq, bk, bv);

    // q/k energy-operand packs
    packA_q_kernel<<<dim3(4, 2, BB*HH), tb>>>();
    packA_k_kernel<<<dim3(4, 2, BB*HH), tb>>>();
    packB_q_kernel<<<dim3(4, 4, BB*8), 256>>>();
    packB_k_kernel<<<dim3(4, 4, BB*8), 256>>>();

    // v H-orientation from packed vWkm
    v_packH_kernel<<<(BB*64*64*128)/256, 256>>>();

    // energies (HMMA) + per-orientation stats
    energy_H_mma_kernel<<<dim3(1, 1, BB*WW), 256>>>();
    energy_W_mma_kernel<<<dim3(1, 1, BB*HH), 256>>>();

    combine_stat_kernel<<<(BB*HWW)/256, 256>>>();

    finalize_H_kernel<<<dim3(4, 4, BB*WW), tb>>>();
    finalize_W_kernel<<<dim3(4, 4, BB*HH), tb>>>();

    // aggregation (HMMA); agg_W fuses +x
    agg_H_mma_kernel<<<dim3(4, 1, BB*WW), 256>>>();
    agg_W_mma_kernel<<<dim3(4, 1, BB*HH), 256>>>(out, x);

    combine_kernel<<<dim3(WW/32, HH/32, BB*CC), tb>>>(out);
}

// round 11
// speedup vs baseline: 2.8803x; 1.0259x over previous
#include <cuda_runtime.h>
#include <cuda_bf16.h>
#include <cstdint>

#define BB 8
#define CC 512
#define DQ 64
#define HH 128
#define WW 128
#define HWW 16384
#define GAMMA_ 1.0f

// ---------------- scratch (device globals; no allocation) ----------------
__device__ float g_q [BB*DQ*HWW];        // [B,DQ,H,W]
__device__ float g_k [BB*DQ*HWW];        // [B,DQ,H,W]
__device__ float g_oH[BB*WW*CC*HH];      // [B,W,C,H]
__device__ float2 g_statH[BB*WW*HH];     // per (b,w,h): partial (max, sum) over H rows
__device__ float2 g_statW[BB*HH*WW];     // per (b,h,w): partial over W rows
__device__ float g_fH[BB*WW*HH];         // column factors for agg_H
__device__ float g_fW[BB*HH*WW];         // column factors for agg_W

// packed bf16 hi/lo (uint32 = two consecutive-K bf16, low half = even k)
__device__ uint32_t g_Wp_h[256*640];               // [kp][m]
__device__ uint32_t g_Wp_l[256*640];
// K-major operands for aggregation ([slice][kp=64][cols])
__device__ uint32_t g_vWkm_h[(size_t)BB*HH*64*512]; // [b*HH+h][wp][c]
__device__ uint32_t g_vWkm_l[(size_t)BB*HH*64*512];
__device__ uint32_t g_vHkm_h[(size_t)BB*WW*64*512]; // [b*WW+w][hp][c]
__device__ uint32_t g_vHkm_l[(size_t)BB*WW*64*512];
__device__ uint32_t g_aHkm_h[(size_t)BB*WW*64*128]; // [b*WW+w][gp][h]  (unnormalized)
__device__ uint32_t g_aHkm_l[(size_t)BB*WW*64*128];
__device__ uint32_t g_aWkm_h[(size_t)BB*HH*64*128]; // [b*HH+h][vp][w]  (unnormalized)
__device__ uint32_t g_aWkm_l[(size_t)BB*HH*64*128];
// K-major operands for energy ([slice][kp=32][128])
__device__ uint32_t g_qWkm_h[(size_t)BB*HH*32*128]; // [b*HH+h][dp][w]
__device__ uint32_t g_qWkm_l[(size_t)BB*HH*32*128];
__device__ uint32_t g_kWkm_h[(size_t)BB*HH*32*128];
__device__ uint32_t g_kWkm_l[(size_t)BB*HH*32*128];
__device__ uint32_t g_qHkm_h[(size_t)BB*WW*32*128]; // [b*WW+w][dp][h]
__device__ uint32_t g_qHkm_l[(size_t)BB*WW*32*128];
__device__ uint32_t g_kHkm_h[(size_t)BB*WW*32*128];
__device__ uint32_t g_kHkm_l[(size_t)BB*WW*32*128];

// ---------------- helpers ----------------
__device__ __forceinline__ void split_pack(float v0, float v1, uint32_t& hi, uint32_t& lo){
    __nv_bfloat16 h0 = __float2bfloat16(v0);
    __nv_bfloat16 h1 = __float2bfloat16(v1);
    __nv_bfloat16 l0 = __float2bfloat16(v0 - __bfloat162float(h0));
    __nv_bfloat16 l1 = __float2bfloat16(v1 - __bfloat162float(h1));
    hi = ((uint32_t)__bfloat16_as_ushort(h1) << 16) | (uint32_t)__bfloat16_as_ushort(h0);
    lo = ((uint32_t)__bfloat16_as_ushort(l1) << 16) | (uint32_t)__bfloat16_as_ushort(l0);
}
__device__ __forceinline__ float b2f_lo(uint32_t u){
    return __bfloat162float(__ushort_as_bfloat16((unsigned short)(u & 0xffffu)));
}
__device__ __forceinline__ float b2f_hi(uint32_t u){
    return __bfloat162float(__ushort_as_bfloat16((unsigned short)(u >> 16)));
}
__device__ __forceinline__ void mma_bf16(float* c, const uint32_t* a, const uint32_t* b){
    asm volatile("mma.sync.aligned.m16n8k16.row.col.f32.bf16.bf16.f32 "
        "{%0,%1,%2,%3}, {%4,%5,%6,%7}, {%8,%9}, {%0,%1,%2,%3};"
        : "+f"(c[0]), "+f"(c[1]), "+f"(c[2]), "+f"(c[3])
        : "r"(a[0]), "r"(a[1]), "r"(a[2]), "r"(a[3]), "r"(b[0]), "r"(b[1]));
}

// ---------------- pack W (tiny) ----------------
__global__ void __launch_bounds__(256) pack_W_kernel(const float* __restrict__ Wq,
                                                     const float* __restrict__ Wk,
                                                     const float* __restrict__ Wv)
{
    int u = blockIdx.x * 256 + threadIdx.x;
    if (u >= 256*160) return;
    int kp = u / 160;
    int m4 = u - kp*160;
    int m = m4*4;
    int c0 = 2*kp, c1 = 2*kp+1;
    float v0[4], v1[4];
    #pragma unroll
    for (int j = 0; j < 4; j++) {
        int mm = m + j;
        if (mm < 64)       { v0[j] = Wq[(size_t)c0*DQ + mm];       v1[j] = Wq[(size_t)c1*DQ + mm]; }
        else if (mm < 128) { v0[j] = Wk[(size_t)c0*DQ + mm-64];    v1[j] = Wk[(size_t)c1*DQ + mm-64]; }
        else               { v0[j] = Wv[(size_t)c0*CC + mm-128];   v1[j] = Wv[(size_t)c1*CC + mm-128]; }
    }
    uint4 hi, lo;
    split_pack(v0[0], v1[0], hi.x, lo.x);
    split_pack(v0[1], v1[1], hi.y, lo.y);
    split_pack(v0[2], v1[2], hi.z, lo.z);
    split_pack(v0[3], v1[3], hi.w, lo.w);
    *(uint4*)(g_Wp_h + (size_t)kp*640 + m) = hi;
    *(uint4*)(g_Wp_l + (size_t)kp*640 + m) = lo;
}

// ---------------- HMMA projection GEMM (validated R8) ----------------
__global__ void __launch_bounds__(256) mma_proj_kernel(
    const float* __restrict__ x,
    const float* __restrict__ bq, const float* __restrict__ bk, const float* __restrict__ bvv)
{
    __shared__ uint32_t sAh[16][136], sAl[16][136], sBh[16][136], sBl[16][136];

    const int tid = threadIdx.x;
    const int wid = tid >> 5, lane = tid & 31;
    const int gid = lane >> 2, tig = lane & 3;
    const int wm0 = (wid >> 2) * 64;
    const int wn0 = (wid & 3) * 32;
    const int mTile = blockIdx.x * 128;
    const int nTile = blockIdx.y * 128;
    const int b = blockIdx.z;

    float acc[4][4][4];
    #pragma unroll
    for (int i = 0; i < 4; i++)
        #pragma unroll
        for (int j = 0; j < 4; j++)
            #pragma unroll
            for (int r = 0; r < 4; r++) acc[i][j][r] = 0.f;

    const float* xB = x + (size_t)b*CC*HWW + nTile;

    for (int it = 0; it < 16; ++it) {
        const int kp0 = it * 16;
        #pragma unroll
        for (int i = 0; i < 2; i++) {
            int f = tid + i*256;
            int kp = f >> 5, c4 = (f & 31) * 4;
            *(uint4*)&sAh[kp][c4] = *(const uint4*)&g_Wp_h[(size_t)(kp0+kp)*640 + mTile + c4];
            *(uint4*)&sAl[kp][c4] = *(const uint4*)&g_Wp_l[(size_t)(kp0+kp)*640 + mTile + c4];
            const float* p0 = xB + (size_t)(2*(kp0+kp))*HWW + c4;
            float4 r0 = *(const float4*)p0;
            float4 r1 = *(const float4*)(p0 + HWW);
            uint4 bh4, bl4;
            split_pack(r0.x, r1.x, bh4.x, bl4.x);
            split_pack(r0.y, r1.y, bh4.y, bl4.y);
            split_pack(r0.z, r1.z, bh4.z, bl4.z);
            split_pack(r0.w, r1.w, bh4.w, bl4.w);
            *(uint4*)&sBh[kp][c4] = bh4;
            *(uint4*)&sBl[kp][c4] = bl4;
        }
        __syncthreads();
        #pragma unroll
        for (int ks = 0; ks < 2; ks++) {
            const int kb = ks * 8;
            uint32_t ah[4][4], al[4][4], bh[4][2], bl[4][2];
            #pragma unroll
            for (int mi = 0; mi < 4; mi++) {
                int m = wm0 + mi*16 + gid;
                ah[mi][0] = sAh[kb+tig  ][m];
                ah[mi][1] = sAh[kb+tig  ][m+8];
                ah[mi][2] = sAh[kb+tig+4][m];
                ah[mi][3] = sAh[kb+tig+4][m+8];
                al[mi][0] = sAl[kb+tig  ][m];
                al[mi][1] = sAl[kb+tig  ][m+8];
                al[mi][2] = sAl[kb+tig+4][m];
                al[mi][3] = sAl[kb+tig+4][m+8];
            }
            #pragma unroll
            for (int nj = 0; nj < 4; nj++) {
                int n = wn0 + nj*8 + gid;
                bh[nj][0] = sBh[kb+tig  ][n];
                bh[nj][1] = sBh[kb+tig+4][n];
                bl[nj][0] = sBl[kb+tig  ][n];
                bl[nj][1] = sBl[kb+tig+4][n];
            }
            #pragma unroll
            for (int mi = 0; mi < 4; mi++)
                #pragma unroll
                for (int nj = 0; nj < 4; nj++) {
                    mma_bf16(acc[mi][nj], ah[mi], bh[nj]);
                    mma_bf16(acc[mi][nj], ah[mi], bl[nj]);
                    mma_bf16(acc[mi][nj], al[mi], bh[nj]);
                }
        }
        __syncthreads();
    }

    if (mTile == 0) {
        #pragma unroll
        for (int mi = 0; mi < 4; mi++) {
            #pragma unroll
            for (int half = 0; half < 2; half++) {
                int row = wm0 + mi*16 + gid + half*8;
                float bias; float* optr;
                if (row < 64) { bias = bq[row];    optr = g_q + ((size_t)b*DQ + row)     *HWW; }
                else          { bias = bk[row-64]; optr = g_k + ((size_t)b*DQ + (row-64))*HWW; }
                #pragma unroll
                for (int nj = 0; nj < 4; nj++) {
                    int col = nTile + wn0 + nj*8 + 2*tig;
                    float2 f2;
                    f2.x = acc[mi][nj][half*2+0] + bias;
                    f2.y = acc[mi][nj][half*2+1] + bias;
                    *(float2*)(optr + col) = f2;
                }
            }
        }
    } else {
        const int hIdx = blockIdx.y;
        #pragma unroll
        for (int mi = 0; mi < 4; mi++) {
            #pragma unroll
            for (int half = 0; half < 2; half++) {
                int c = mTile - 128 + wm0 + mi*16 + gid + half*8;
                float bias = bvv[c];
                #pragma unroll
                for (int nj = 0; nj < 4; nj++) {
                    int col = wn0 + nj*8 + 2*tig;
                    uint32_t hh, ll;
                    split_pack(acc[mi][nj][half*2+0] + bias,
                               acc[mi][nj][half*2+1] + bias, hh, ll);
                    size_t o = ((size_t)(b*HH + hIdx)*64 + (col>>1))*512 + c;
                    g_vWkm_h[o] = hh; g_vWkm_l[o] = ll;
                }
            }
        }
    }
}

// ---------------- v pack H-orientation from packed vWkm (validated R8) ----------
__global__ void __launch_bounds__(256) v_packH_kernel()
{
    int u = blockIdx.x*256 + threadIdx.x;
    int c4 = u & 127;
    int hp = (u >> 7) & 63;
    int wp = (u >> 13) & 63;
    int b  = u >> 19;
    size_t i0 = ((size_t)(b*HH + 2*hp  )*64 + wp)*512 + c4*4;
    size_t i1 = ((size_t)(b*HH + 2*hp+1)*64 + wp)*512 + c4*4;
    uint4 h0 = *(const uint4*)(g_vWkm_h + i0), l0 = *(const uint4*)(g_vWkm_l + i0);
    uint4 h1 = *(const uint4*)(g_vWkm_h + i1), l1 = *(const uint4*)(g_vWkm_l + i1);
    uint4 oh0, ol0, oh1, ol1;
    split_pack(b2f_lo(h0.x)+b2f_lo(l0.x), b2f_lo(h1.x)+b2f_lo(l1.x), oh0.x, ol0.x);
    split_pack(b2f_lo(h0.y)+b2f_lo(l0.y), b2f_lo(h1.y)+b2f_lo(l1.y), oh0.y, ol0.y);
    split_pack(b2f_lo(h0.z)+b2f_lo(l0.z), b2f_lo(h1.z)+b2f_lo(l1.z), oh0.z, ol0.z);
    split_pack(b2f_lo(h0.w)+b2f_lo(l0.w), b2f_lo(h1.w)+b2f_lo(l1.w), oh0.w, ol0.w);
    split_pack(b2f_hi(h0.x)+b2f_hi(l0.x), b2f_hi(h1.x)+b2f_hi(l1.x), oh1.x, ol1.x);
    split_pack(b2f_hi(h0.y)+b2f_hi(l0.y), b2f_hi(h1.y)+b2f_hi(l1.y), oh1.y, ol1.y);
    split_pack(b2f_hi(h0.z)+b2f_hi(l0.z), b2f_hi(h1.z)+b2f_hi(l1.z), oh1.z, ol1.z);
    split_pack(b2f_hi(h0.w)+b2f_hi(l0.w), b2f_hi(h1.w)+b2f_hi(l1.w), oh1.w, ol1.w);
    size_t o0 = ((size_t)(b*WW + 2*wp  )*64 + hp)*512 + c4*4;
    size_t o1 = ((size_t)(b*WW + 2*wp+1)*64 + hp)*512 + c4*4;
    *(uint4*)(g_vHkm_h + o0) = oh0; *(uint4*)(g_vHkm_l + o0) = ol0;
    *(uint4*)(g_vHkm_h + o1) = oh1; *(uint4*)(g_vHkm_l + o1) = ol1;
}

// ---------------- packA/packB: q/k energy operands (validated R7) ----------------
__device__ __forceinline__ void packA_body(const float* __restrict__ src,
                                           uint32_t* __restrict__ dh,
                                           uint32_t* __restrict__ dl)
{
    __shared__ float t[32][33];
    int s = blockIdx.z;
    int b = s >> 7, h = s & 127;
    int w0 = blockIdx.x*32, d0 = blockIdx.y*32;
    int tx = threadIdx.x, ty = threadIdx.y;
    const float* S = src + (size_t)b*DQ*HWW + (size_t)h*WW;
    #pragma unroll
    for (int j = 0; j < 32; j += 8)
        t[ty+j][tx] = S[(size_t)(d0+ty+j)*HWW + w0 + tx];
    __syncthreads();
    #pragma unroll
    for (int j = 0; j < 16; j += 8) {
        int kp = ty + j;
        uint32_t hi, lo;
        split_pack(t[2*kp][tx], t[2*kp+1][tx], hi, lo);
        size_t o = ((size_t)s*32 + (d0>>1) + kp)*128 + w0 + tx;
        dh[o] = hi; dl[o] = lo;
    }
}
__global__ void packA_q_kernel(){ packA_body(g_q, g_qWkm_h, g_qWkm_l); }
__global__ void packA_k_kernel(){ packA_body(g_k, g_kWkm_h, g_kWkm_l); }

__device__ __forceinline__ void packB_body(const float* __restrict__ src,
                                           uint32_t* __restrict__ dh,
                                           uint32_t* __restrict__ dl)
{
    __shared__ float t[8][32][33];
    int z = blockIdx.z;
    int b = z >> 3, d0 = (z & 7) * 8;
    int w0 = blockIdx.x*32, h0 = blockIdx.y*32;
    int tid = threadIdx.x;
    int tx = tid & 31, ty = tid >> 5;
    #pragma unroll
    for (int dd = 0; dd < 8; dd++)
        #pragma unroll
        for (int j = 0; j < 32; j += 8)
            t[dd][ty+j][tx] = src[((size_t)b*DQ + d0+dd)*HWW + (size_t)(h0+ty+j)*WW + w0 + tx];
    __syncthreads();
    #pragma unroll
    for (int it = 0; it < 16; it++) {
        int idx = tid + it*256;
        int hl = idx & 31, wl = (idx >> 5) & 31, dpl = idx >> 10;
        uint32_t hi, lo;
        split_pack(t[2*dpl][hl][wl], t[2*dpl+1][hl][wl], hi, lo);
        size_t o = (((size_t)b*WW + w0 + wl)*32 + (d0>>1) + dpl)*128 + h0 + hl;
        dh[o] = hi; dl[o] = lo;
    }
}
__global__ void __launch_bounds__(256) packB_q_kernel(){ packB_body(g_q, g_qHkm_h, g_qHkm_l); }
__global__ void __launch_bounds__(256) packB_k_kernel(){ packB_body(g_k, g_kHkm_h, g_kHkm_l); }

// ---------------- HMMA energy GEMM -> unnormalized packed att + stat partials ----
template<int MASK>
__device__ __forceinline__ void energy_mma_body(
    const uint32_t* __restrict__ Qh, const uint32_t* __restrict__ Ql,
    const uint32_t* __restrict__ Kh, const uint32_t* __restrict__ Kl,
    uint32_t* __restrict__ dh, uint32_t* __restrict__ dl,
    float2* __restrict__ statOut)
{
    __shared__ uint32_t sAh[16][136], sAl[16][136], sBh[16][136], sBl[16][136];
    __shared__ float red[128][17];
    __shared__ float rmax[128];

    const int tid = threadIdx.x;
    const int wid = tid >> 5, lane = tid & 31;
    const int gid = lane >> 2, tig = lane & 3;
    const int wm0 = (wid >> 2) * 64;
    const int wn0 = (wid & 3) * 32;
    const int cg  = (wid & 3) * 4 + tig;
    const int s = blockIdx.z;

    const uint32_t* Qh_s = Qh + (size_t)s*32*128;
    const uint32_t* Ql_s = Ql + (size_t)s*32*128;
    const uint32_t* Kh_s = Kh + (size_t)s*32*128;
    const uint32_t* Kl_s = Kl + (size_t)s*32*128;

    float acc[4][4][4];
    #pragma unroll
    for (int i = 0; i < 4; i++)
        #pragma unroll
        for (int j = 0; j < 4; j++)
            #pragma unroll
            for (int r = 0; r < 4; r++) acc[i][j][r] = 0.f;

    for (int ch = 0; ch < 2; ++ch) {
        const int kp0 = ch * 16;
        #pragma unroll
        for (int i = 0; i < 2; i++) {
            int f = tid + i*256;
            int kp = f >> 5, c4 = (f & 31) * 4;
            *(uint4*)&sAh[kp][c4] = *(const uint4*)(Qh_s + (size_t)(kp0+kp)*128 + c4);
            *(uint4*)&sAl[kp][c4] = *(const uint4*)(Ql_s + (size_t)(kp0+kp)*128 + c4);
            *(uint4*)&sBh[kp][c4] = *(const uint4*)(Kh_s + (size_t)(kp0+kp)*128 + c4);
            *(uint4*)&sBl[kp][c4] = *(const uint4*)(Kl_s + (size_t)(kp0+kp)*128 + c4);
        }
        __syncthreads();
        #pragma unroll
        for (int ks = 0; ks < 2; ks++) {
            const int kb = ks * 8;
            uint32_t ah[4][4], al[4][4], bh[4][2], bl[4][2];
            #pragma unroll
            for (int mi = 0; mi < 4; mi++) {
                int m = wm0 + mi*16 + gid;
                ah[mi][0] = sAh[kb+tig  ][m];
                ah[mi][1] = sAh[kb+tig  ][m+8];
                ah[mi][2] = sAh[kb+tig+4][m];
                ah[mi][3] = sAh[kb+tig+4][m+8];
                al[mi][0] = sAl[kb+tig  ][m];
                al[mi][1] = sAl[kb+tig  ][m+8];
                al[mi][2] = sAl[kb+tig+4][m];
                al[mi][3] = sAl[kb+tig+4][m+8];
            }
            #pragma unroll
            for (int nj = 0; nj < 4; nj++) {
                int n = wn0 + nj*8 + gid;
                bh[nj][0] = sBh[kb+tig  ][n];
                bh[nj][1] = sBh[kb+tig+4][n];
                bl[nj][0] = sBl[kb+tig  ][n];
                bl[nj][1] = sBl[kb+tig+4][n];
            }
            #pragma unroll
            for (int mi = 0; mi < 4; mi++)
                #pragma unroll
                for (int nj = 0; nj < 4; nj++) {
                    mma_bf16(acc[mi][nj], ah[mi], bh[nj]);
                    mma_bf16(acc[mi][nj], ah[mi], bl[nj]);
                    mma_bf16(acc[mi][nj], al[mi], bh[nj]);
                }
        }
        __syncthreads();
    }

    const float NINF = __int_as_float(0xff800000);
    if (MASK) {
        #pragma unroll
        for (int mi = 0; mi < 4; mi++)
            #pragma unroll
            for (int half = 0; half < 2; half++) {
                int row = wm0 + mi*16 + gid + half*8;
                #pragma unroll
                for (int nj = 0; nj < 4; nj++) {
                    int col = wn0 + nj*8 + 2*tig;
                    if (row == col)   acc[mi][nj][half*2+0] = NINF;
                    if (row == col+1) acc[mi][nj][half*2+1] = NINF;
                }
            }
    }

    // phase 1: per-row max
    #pragma unroll
    for (int mi = 0; mi < 4; mi++)
        #pragma unroll
        for (int half = 0; half < 2; half++) {
            int row = wm0 + mi*16 + gid + half*8;
            float m8 = NINF;
            #pragma unroll
            for (int nj = 0; nj < 4; nj++) {
                m8 = fmaxf(m8, acc[mi][nj][half*2+0]);
                m8 = fmaxf(m8, acc[mi][nj][half*2+1]);
            }
            red[row][cg] = m8;
        }
    __syncthreads();
    if (tid < 128) {
        float m = red[tid][0];
        #pragma unroll
        for (int j = 1; j < 16; j++) m = fmaxf(m, red[tid][j]);
        rmax[tid] = m;
    }
    __syncthreads();

    // phase 2: exp, sum, and write packed unnormalized attention (K-major)
    #pragma unroll
    for (int mi = 0; mi < 4; mi++)
        #pragma unroll
        for (int half = 0; half < 2; half++) {
            int row = wm0 + mi*16 + gid + half*8;
            float rm = rmax[row];
            float s8 = 0.f;
            #pragma unroll
            for (int nj = 0; nj < 4; nj++) {
                int col = wn0 + nj*8 + 2*tig;
                float e0 = __expf(acc[mi][nj][half*2+0] - rm);
                float e1 = __expf(acc[mi][nj][half*2+1] - rm);
                s8 += e0 + e1;
                uint32_t hi, lo;
                split_pack(e0, e1, hi, lo);
                size_t o = (size_t)s*8192 + (size_t)(col>>1)*128 + row;
                dh[o] = hi; dl[o] = lo;
            }
            red[row][cg] = s8;
        }
    __syncthreads();
    if (tid < 128) {
        float ssum = red[tid][0];
        #pragma unroll
        for (int j = 1; j < 16; j++) ssum += red[tid][j];
        statOut[(size_t)s*128 + tid] = make_float2(rmax[tid], ssum);
    }
}
__global__ void __launch_bounds__(256) energy_H_mma_kernel(){
    energy_mma_body<1>(g_qHkm_h, g_qHkm_l, g_kHkm_h, g_kHkm_l,
                       g_aHkm_h, g_aHkm_l, g_statH);
}
__global__ void __launch_bounds__(256) energy_W_mma_kernel(){
    energy_mma_body<0>(g_qWkm_h, g_qWkm_l, g_kWkm_h, g_kWkm_l,
                       g_aWkm_h, g_aWkm_l, g_statW);
}

// ---------------- merge stats -> per-orientation column factors ----------------
__global__ void __launch_bounds__(256) combine_stat_kernel()
{
    int u = blockIdx.x*256 + threadIdx.x;   // b*HWW + h*WW + w
    int b = u >> 14;
    int hw = u & 16383;
    int h = hw >> 7, w = hw & 127;
    size_t iH = (size_t)(b*WW + w)*128 + h;
    size_t iW = (size_t)(b*HH + h)*128 + w;
    float2 sh = g_statH[iH];
    float2 sw = g_statW[iW];
    float m = fmaxf(sh.x, sw.x);
    float eh = __expf(sh.x - m), ew = __expf(sw.x - m);
    float invZ = 1.0f / (sh.y*eh + sw.y*ew);
    g_fH[iH] = eh * invZ;
    g_fW[iW] = ew * invZ;
}

// ---------------- HMMA aggregation with per-column factor (+optional fused +x) ----
__device__ __forceinline__ void agg_mma_body(
    const uint32_t* __restrict__ Vh, const uint32_t* __restrict__ Vl,
    const uint32_t* __restrict__ Ah, const uint32_t* __restrict__ Al,
    const float* __restrict__ fac,
    float* __restrict__ O, long oB, long oS, long oRow,
    const float* __restrict__ xAdd)
{
    __shared__ uint32_t sAh[16][136], sAl[16][136], sBh[16][136], sBl[16][136];
    __shared__ float sFac[128];

    const int tid = threadIdx.x;
    const int wid = tid >> 5, lane = tid & 31;
    const int gid = lane >> 2, tig = lane & 3;
    const int wm0 = (wid >> 2) * 64;
    const int wn0 = (wid & 3) * 32;
    const int mTile = blockIdx.x * 128;
    const int s = blockIdx.z;
    const int b = s >> 7, ss = s & 127;

    const uint32_t* Vh_s = Vh + (size_t)s*64*512 + mTile;
    const uint32_t* Vl_s = Vl + (size_t)s*64*512 + mTile;
    const uint32_t* Ah_s = Ah + (size_t)s*64*128;
    const uint32_t* Al_s = Al + (size_t)s*64*128;
    const size_t oBase = (size_t)b*oB + (size_t)ss*oS + (size_t)mTile*oRow;
    float* O_s = O + oBase;
    const float* X_s = xAdd ? (xAdd + oBase) : nullptr;

    if (tid < 128) sFac[tid] = fac[(size_t)s*128 + tid];

    float acc[4][4][4];
    #pragma unroll
    for (int i = 0; i < 4; i++)
        #pragma unroll
        for (int j = 0; j < 4; j++)
            #pragma unroll
            for (int r = 0; r < 4; r++) acc[i][j][r] = 0.f;

    for (int ch = 0; ch < 4; ++ch) {
        const int kp0 = ch * 16;
        #pragma unroll
        for (int i = 0; i < 2; i++) {
            int f = tid + i*256;
            int kp = f >> 5, c4 = (f & 31) * 4;
            *(uint4*)&sAh[kp][c4] = *(const uint4*)(Vh_s + (size_t)(kp0+kp)*512 + c4);
            *(uint4*)&sAl[kp][c4] = *(const uint4*)(Vl_s + (size_t)(kp0+kp)*512 + c4);
            *(uint4*)&sBh[kp][c4] = *(const uint4*)(Ah_s + (size_t)(kp0+kp)*128 + c4);
            *(uint4*)&sBl[kp][c4] = *(const uint4*)(Al_s + (size_t)(kp0+kp)*128 + c4);
        }
        __syncthreads();
        #pragma unroll
        for (int ks = 0; ks < 2; ks++) {
            const int kb = ks * 8;
            uint32_t ah[4][4], al[4][4], bh[4][2], bl[4][2];
            #pragma unroll
            for (int mi = 0; mi < 4; mi++) {
                int m = wm0 + mi*16 + gid;
                ah[mi][0] = sAh[kb+tig  ][m];
                ah[mi][1] = sAh[kb+tig  ][m+8];
                ah[mi][2] = sAh[kb+tig+4][m];
                ah[mi][3] = sAh[kb+tig+4][m+8];
                al[mi][0] = sAl[kb+tig  ][m];
                al[mi][1] = sAl[kb+tig  ][m+8];
                al[mi][2] = sAl[kb+tig+4][m];
                al[mi][3] = sAl[kb+tig+4][m+8];
            }
            #pragma unroll
            for (int nj = 0; nj < 4; nj++) {
                int n = wn0 + nj*8 + gid;
                bh[nj][0] = sBh[kb+tig  ][n];
                bh[nj][1] = sBh[kb+tig+4][n];
                bl[nj][0] = sBl[kb+tig  ][n];
                bl[nj][1] = sBl[kb+tig+4][n];
            }
            #pragma unroll
            for (int mi = 0; mi < 4; mi++)
                #pragma unroll
                for (int nj = 0; nj < 4; nj++) {
                    mma_bf16(acc[mi][nj], ah[mi], bh[nj]);
                    mma_bf16(acc[mi][nj], ah[mi], bl[nj]);
                    mma_bf16(acc[mi][nj], al[mi], bh[nj]);
                }
        }
        __syncthreads();
    }

    #pragma unroll
    for (int mi = 0; mi < 4; mi++) {
        #pragma unroll
        for (int half = 0; half < 2; half++) {
            int rowL = wm0 + mi*16 + gid + half*8;
            size_t roff = (size_t)rowL*oRow;
            #pragma unroll
            for (int nj = 0; nj < 4; nj++) {
                int col = wn0 + nj*8 + 2*tig;
                float2 f2;
                f2.x = acc[mi][nj][half*2+0] * sFac[col];
                f2.y = acc[mi][nj][half*2+1] * sFac[col+1];
                if (X_s) {
                    float2 xv = *(const float2*)(X_s + roff + col);
                    f2.x += xv.x; f2.y += xv.y;
                }
                *(float2*)(O_s + roff + col) = f2;
            }
        }
    }
}
__global__ void __launch_bounds__(256) agg_H_mma_kernel(){
    agg_mma_body(g_vHkm_h, g_vHkm_l, g_aHkm_h, g_aHkm_l, g_fH, g_oH,
                 (long)WW*CC*HH, (long)CC*HH, (long)HH, nullptr);
}
__global__ void __launch_bounds__(256) agg_W_mma_kernel(float* __restrict__ out,
                                                        const float* __restrict__ x){
    agg_mma_body(g_vWkm_h, g_vWkm_l, g_aWkm_h, g_aWkm_l, g_fW, out,
                 (long)CC*HWW, (long)WW, (long)HWW, x);
}

// ---------------- combine: out += GAMMA*out_H^T  (out already = out_W + x) ----------
__global__ void combine_kernel(float* __restrict__ out)
{
    __shared__ float t[32][33];
    int bc = blockIdx.z;
    int b = bc >> 9, c = bc & 511;
    int w0 = blockIdx.x*32, h0 = blockIdx.y*32;
    int tx = threadIdx.x, ty = threadIdx.y;
    #pragma unroll
    for (int k = 0; k < 32; k += 8) {
        int w = w0 + ty + k;
        int h = h0 + tx;
        t[ty+k][tx] = g_oH[(((size_t)b*WW + w)*CC + c)*HH + h];
    }
    __syncthreads();
    #pragma unroll
    for (int k = 0; k < 32; k += 8) {
        int h = h0 + ty + k;
        int w = w0 + tx;
        size_t idx = ((size_t)bc*HH + h)*WW + w;
        out[idx] = GAMMA_*t[tx][ty+k] + out[idx];
    }
}

// ---------------- launch ----------------
extern "C" void kernel_launch(void* const* d_in, const int* in_sizes, int n_in,
                              void* d_out, int out_size)
{
    const float* x  = (const float*)d_in[0];
    const float* Wq = (const float*)d_in[1];
    const float* bq = (const float*)d_in[2];
    const float* Wk = (const float*)d_in[3];
    const float* bk = (const float*)d_in[4];
    const float* Wv = (const float*)d_in[5];
    const float* bv = (const float*)d_in[6];
    float* out = (float*)d_out;

    dim3 tb(32, 8);

    pack_W_kernel<<<160, 256>>>(Wq, Wk, Wv);

    mma_proj_kernel<<<dim3(5, HWW/128, BB), 256>>>(x, bq, bk, bv);

    packA_q_kernel<<<dim3(4, 2, BB*HH), tb>>>();
    packA_k_kernel<<<dim3(4, 2, BB*HH), tb>>>();
    packB_q_kernel<<<dim3(4, 4, BB*8), 256>>>();
    packB_k_kernel<<<dim3(4, 4, BB*8), 256>>>();

    v_packH_kernel<<<(BB*64*64*128)/256, 256>>>();

    energy_H_mma_kernel<<<dim3(1, 1, BB*WW), 256>>>();
    energy_W_mma_kernel<<<dim3(1, 1, BB*HH), 256>>>();

    combine_stat_kernel<<<(BB*HWW)/256, 256>>>();

    agg_H_mma_kernel<<<dim3(4, 1, BB*WW), 256>>>();
    agg_W_mma_kernel<<<dim3(4, 1, BB*HH), 256>>>(out, x);

    combine_kernel<<<dim3(WW/32, HH/32, BB*CC), tb>>>(out);
}